// round 1
// baseline (speedup 1.0000x reference)
#include <cuda_runtime.h>
#include <math.h>

#define NN 50000
#define NE 800000
#define H 128
#define LAY 3
#define NG 512
#define NOUT 10
#define HH (H*H)

// ---------------- scratch (static device globals; no runtime alloc) --------
__device__ float d_hA[NN*H];
__device__ float d_hB[NN*H];
__device__ float d_mean[NN*H];
__device__ float d_sum[NN*H];
__device__ float d_gcn[NN*H];
__device__ float d_Wcomb[LAY*4*HH];
__device__ float d_na[LAY*4];
__device__ float d_ro[(LAY+1)*3];
__device__ int   d_deg[NN];
__device__ int   d_rowptr[NN+1];
__device__ int   d_cursor[NN];
__device__ int   d_csr[NE];
__device__ float d_invdeg[NN];
__device__ float d_invsqrt[NN];
__device__ int   d_bhist[NG];
__device__ int   d_gstart[NG+1];
__device__ float d_gfeat[NG*(LAY+1)*H];

// ---------------- small prep kernels ---------------------------------------
__global__ void k_zero() {
    int i = blockIdx.x*blockDim.x + threadIdx.x;
    if (i < NN) d_deg[i] = 0;
    if (i < NG) d_bhist[i] = 0;
}

__global__ void k_softmax(const float* __restrict__ lna, const float* __restrict__ lro) {
    if (threadIdx.x == 0) {
        for (int l = 0; l < LAY; l++) {
            float m = -1e30f;
            for (int j = 0; j < 4; j++) m = fmaxf(m, lna[l*4+j]);
            float e[4]; float s = 0.f;
            for (int j = 0; j < 4; j++) { e[j] = expf(lna[l*4+j]-m); s += e[j]; }
            for (int j = 0; j < 4; j++) d_na[l*4+j] = e[j]/s;
        }
        for (int l = 0; l < LAY+1; l++) {
            float m = -1e30f;
            for (int j = 0; j < 3; j++) m = fmaxf(m, lro[l*3+j]);
            float e[3]; float s = 0.f;
            for (int j = 0; j < 3; j++) { e[j] = expf(lro[l*3+j]-m); s += e[j]; }
            for (int j = 0; j < 3; j++) d_ro[l*3+j] = e[j]/s;
        }
    }
}

// Combined per-layer weights: 4 source matrices of [H,H]
//   s0 (h)        : w1*W1 + w2*W3 + w3*W4
//   s1 (agg_mean) : w1*W2
//   s2 (agg_sum)  : w2*W3
//   s3 (gcn_agg)  : w0*W0
__global__ void k_wcomb(const float* __restrict__ Wna) {
    int i = blockIdx.x*blockDim.x + threadIdx.x;
    if (i >= LAY*4*HH) return;
    int l = i/(4*HH); int r = i%(4*HH); int s = r/HH; int e = r%HH;
    const float* W  = Wna + l*5*HH;
    const float* na = d_na + l*4;
    float v;
    if (s == 0)      v = na[1]*W[1*HH+e] + na[2]*W[3*HH+e] + na[3]*W[4*HH+e];
    else if (s == 1) v = na[1]*W[2*HH+e];
    else if (s == 2) v = na[2]*W[3*HH+e];
    else             v = na[0]*W[0*HH+e];
    d_Wcomb[i] = v;
}

__global__ void k_hist(const int* __restrict__ dst, const int* __restrict__ batch) {
    int i = blockIdx.x*blockDim.x + threadIdx.x;
    int stride = gridDim.x*blockDim.x;
    for (int e = i; e < NE; e += stride) atomicAdd(&d_deg[dst[e]], 1);
    for (int n = i; n < NN; n += stride) atomicAdd(&d_bhist[batch[n]], 1);
}

// single-block exclusive scan, out has n+1 entries (out[n] = total)
__global__ void k_scan(const int* __restrict__ in, int* __restrict__ out, int n) {
    __shared__ int wsum[32];
    __shared__ int carry;
    if (threadIdx.x == 0) carry = 0;
    __syncthreads();
    int lane = threadIdx.x & 31, warp = threadIdx.x >> 5;
    for (int base = 0; base < n; base += 1024) {
        int i = base + (int)threadIdx.x;
        int v = (i < n) ? in[i] : 0;
        int x = v;
        #pragma unroll
        for (int o = 1; o < 32; o <<= 1) {
            int y = __shfl_up_sync(0xffffffffu, x, o);
            if (lane >= o) x += y;
        }
        if (lane == 31) wsum[warp] = x;
        __syncthreads();
        if (warp == 0) {
            int s = wsum[lane];
            #pragma unroll
            for (int o = 1; o < 32; o <<= 1) {
                int y = __shfl_up_sync(0xffffffffu, s, o);
                if (lane >= o) s += y;
            }
            wsum[lane] = s;
        }
        __syncthreads();
        int incl  = x + (warp ? wsum[warp-1] : 0);
        int total = wsum[31];
        if (i < n) out[i] = carry + incl - v;
        __syncthreads();
        if (threadIdx.x == 0) carry += total;
        __syncthreads();
    }
    if (threadIdx.x == 0) out[n] = carry;
}

__global__ void k_cursor_stats() {
    int i = blockIdx.x*blockDim.x + threadIdx.x;
    if (i >= NN) return;
    d_cursor[i] = d_rowptr[i];
    int c = d_deg[i];
    float m = (float)(c > 1 ? c : 1);
    d_invdeg[i]  = 1.0f/m;
    d_invsqrt[i] = rsqrtf(m);
}

__global__ void k_scatter(const int* __restrict__ src, const int* __restrict__ dst) {
    int i = blockIdx.x*blockDim.x + threadIdx.x;
    int stride = gridDim.x*blockDim.x;
    for (int e = i; e < NE; e += stride) {
        int d = dst[e];
        int p = atomicAdd(&d_cursor[d], 1);
        d_csr[p] = src[e];
    }
}

// ---------------- aggregation: one warp per dst node ------------------------
__global__ void k_aggregate(const float* __restrict__ h) {
    int gw   = (blockIdx.x*blockDim.x + threadIdx.x) >> 5;
    int lane = threadIdx.x & 31;
    if (gw >= NN) return;
    int beg = d_rowptr[gw], end = d_rowptr[gw+1];
    const float4* h4 = reinterpret_cast<const float4*>(h);
    float4 s = {0.f,0.f,0.f,0.f};
    float4 g = {0.f,0.f,0.f,0.f};
    for (int e = beg; e < end; e++) {
        int src  = d_csr[e];
        float is = d_invsqrt[src];
        float4 v = h4[src*32 + lane];
        s.x += v.x;    s.y += v.y;    s.z += v.z;    s.w += v.w;
        g.x += v.x*is; g.y += v.y*is; g.z += v.z*is; g.w += v.w*is;
    }
    float id  = d_invdeg[gw];
    float isd = d_invsqrt[gw];
    int o = gw*32 + lane;
    reinterpret_cast<float4*>(d_sum)[o]  = s;
    float4 mn = {s.x*id, s.y*id, s.z*id, s.w*id};
    reinterpret_cast<float4*>(d_mean)[o] = mn;
    float4 gc = {g.x*isd, g.y*isd, g.z*isd, g.w*isd};
    reinterpret_cast<float4*>(d_gcn)[o]  = gc;
}

// ---------------- multi-source fp32 GEMM: out[M,128] = sum_s A_s @ W_s ------
// 64x128 tile, BK=32, 256 threads, each thread 4x8 outputs
__global__ void __launch_bounds__(256)
k_gemm(const float* __restrict__ A0, const float* __restrict__ A1,
       const float* __restrict__ A2, const float* __restrict__ A3,
       const float* __restrict__ W,  const float* __restrict__ bias,
       float* __restrict__ out, int M, int nsrc, int relu)
{
    __shared__ float As[32][65];
    __shared__ float Bs[32][128];
    const float* srcs[4] = {A0, A1, A2, A3};
    int tid = threadIdx.x;
    int tx = tid & 15, ty = tid >> 4;
    int row0 = blockIdx.x * 64;
    int m0 = ty*4, n0 = tx*8;
    float acc[4][8];
    #pragma unroll
    for (int i = 0; i < 4; i++)
        #pragma unroll
        for (int j = 0; j < 8; j++) acc[i][j] = 0.f;

    for (int s = 0; s < nsrc; s++) {
        const float* A  = srcs[s];
        const float* Wb = W + s*HH;
        for (int kt = 0; kt < 4; kt++) {
            int k0 = kt*32;
            #pragma unroll
            for (int i = 0; i < 8; i++) {
                int idx = tid + i*256;
                int k = idx & 31, m = idx >> 5;
                int r = row0 + m;
                As[k][m] = (r < M) ? A[r*H + k0 + k] : 0.f;
            }
            #pragma unroll
            for (int i = 0; i < 16; i++) {
                int idx = tid + i*256;
                int n = idx & 127, k = idx >> 7;
                Bs[k][n] = Wb[(k0 + k)*H + n];
            }
            __syncthreads();
            #pragma unroll
            for (int kk = 0; kk < 32; kk++) {
                float a[4];
                #pragma unroll
                for (int i = 0; i < 4; i++) a[i] = As[kk][m0 + i];
                float b[8];
                *reinterpret_cast<float4*>(&b[0]) = *reinterpret_cast<const float4*>(&Bs[kk][n0]);
                *reinterpret_cast<float4*>(&b[4]) = *reinterpret_cast<const float4*>(&Bs[kk][n0+4]);
                #pragma unroll
                for (int i = 0; i < 4; i++)
                    #pragma unroll
                    for (int j = 0; j < 8; j++)
                        acc[i][j] += a[i]*b[j];
            }
            __syncthreads();
        }
    }
    #pragma unroll
    for (int i = 0; i < 4; i++) {
        int r = row0 + m0 + i;
        if (r >= M) continue;
        #pragma unroll
        for (int j = 0; j < 8; j++) {
            int c = n0 + j;
            float v = acc[i][j];
            if (bias) v += bias[c];
            if (relu) v = fmaxf(v, 0.f);
            out[r*H + c] = v;
        }
    }
}

// ---------------- readout: one block per graph, one thread per column -------
__global__ void k_readout(const float* __restrict__ h, int layer) {
    int gr = blockIdx.x;
    int c  = threadIdx.x;
    int beg = d_gstart[gr], end = d_gstart[gr+1];
    float s = 0.f, mx = -3.4e38f;
    for (int n = beg; n < end; n++) {
        float v = h[n*H + c];
        s += v;
        mx = fmaxf(mx, v);
    }
    int cnt = end - beg;
    float mean = s / (float)(cnt > 1 ? cnt : 1);
    if (cnt == 0) mx = 0.f;
    const float* w = d_ro + layer*3;
    d_gfeat[gr*((LAY+1)*H) + layer*H + c] = w[0]*mean + w[1]*mx + w[2]*s;
}

// ---------------- head: relu(g @ Wl + bl) @ Wc + bc -------------------------
__global__ void k_head(const float* __restrict__ Wl, const float* __restrict__ bl,
                       const float* __restrict__ Wc, const float* __restrict__ bc,
                       float* __restrict__ out) {
    __shared__ float sg[(LAY+1)*H];
    __shared__ float mid[H];
    int gr = blockIdx.x;
    int t  = threadIdx.x;
    for (int i = t; i < (LAY+1)*H; i += H) sg[i] = d_gfeat[gr*((LAY+1)*H) + i];
    __syncthreads();
    float acc = bl[t];
    for (int k = 0; k < (LAY+1)*H; k++) acc += sg[k]*Wl[k*H + t];
    mid[t] = fmaxf(acc, 0.f);
    __syncthreads();
    if (t < NOUT) {
        float a = bc[t];
        for (int k = 0; k < H; k++) a += mid[k]*Wc[k*NOUT + t];
        out[gr*NOUT + t] = a;
    }
}

// ---------------- launch ----------------------------------------------------
extern "C" void kernel_launch(void* const* d_in, const int* in_sizes, int n_in,
                              void* d_out, int out_size) {
    const float* x      = (const float*)d_in[0];
    const int*   ei     = (const int*)  d_in[1];
    const int*   batch  = (const int*)  d_in[2];
    const float* lin1_W = (const float*)d_in[3];
    const float* lin1_b = (const float*)d_in[4];
    const float* Wna    = (const float*)d_in[5];
    const float* lna    = (const float*)d_in[6];
    const float* lro    = (const float*)d_in[7];
    const float* lout_W = (const float*)d_in[8];
    const float* lout_b = (const float*)d_in[9];
    const float* cls_W  = (const float*)d_in[10];
    const float* cls_b  = (const float*)d_in[11];
    const int* srcp = ei;
    const int* dstp = ei + NE;

    float *hA, *hB, *pmean, *psum, *pgcn, *pWcomb;
    int *pdeg, *prowptr, *pbhist, *pgstart;
    cudaGetSymbolAddress((void**)&hA,      d_hA);
    cudaGetSymbolAddress((void**)&hB,      d_hB);
    cudaGetSymbolAddress((void**)&pmean,   d_mean);
    cudaGetSymbolAddress((void**)&psum,    d_sum);
    cudaGetSymbolAddress((void**)&pgcn,    d_gcn);
    cudaGetSymbolAddress((void**)&pWcomb,  d_Wcomb);
    cudaGetSymbolAddress((void**)&pdeg,    d_deg);
    cudaGetSymbolAddress((void**)&prowptr, d_rowptr);
    cudaGetSymbolAddress((void**)&pbhist,  d_bhist);
    cudaGetSymbolAddress((void**)&pgstart, d_gstart);

    k_zero<<<(NN+255)/256, 256>>>();
    k_softmax<<<1, 32>>>(lna, lro);
    k_wcomb<<<(LAY*4*HH+255)/256, 256>>>(Wna);
    k_hist<<<1024, 256>>>(dstp, batch);
    k_scan<<<1, 1024>>>(pdeg, prowptr, NN);
    k_scan<<<1, 1024>>>(pbhist, pgstart, NG);
    k_cursor_stats<<<(NN+255)/256, 256>>>();
    k_scatter<<<1024, 256>>>(srcp, dstp);

    // h = x @ lin1_W + b   (single-source GEMM)
    k_gemm<<<(NN+63)/64, 256>>>(x, x, x, x, lin1_W, lin1_b, hA, NN, 1, 0);
    k_readout<<<NG, H>>>(hA, 0);

    float* cur = hA;
    float* nxt = hB;
    for (int l = 0; l < LAY; l++) {
        k_aggregate<<<(NN*32+255)/256, 256>>>(cur);
        k_gemm<<<(NN+63)/64, 256>>>(cur, pmean, psum, pgcn,
                                    pWcomb + l*4*HH, nullptr, nxt, NN, 4, 1);
        k_readout<<<NG, H>>>(nxt, l+1);
        float* t = cur; cur = nxt; nxt = t;
    }
    k_head<<<NG, H>>>(lout_W, lout_b, cls_W, cls_b, (float*)d_out);
}

// round 4
// speedup vs baseline: 2.4165x; 2.4165x over previous
#include <cuda_runtime.h>
#include <math.h>
#include <stdint.h>

#define NN 50000
#define NE 800000
#define H 128
#define LAY 3
#define NG 512
#define NOUT 10
#define HH (H*H)
#define NB_SCAN ((NN + 1023) / 1024)

// ---------------- scratch (static device globals) ---------------------------
__device__ float d_hA[NN*H];
__device__ float d_hB[NN*H];
__device__ float d_sum[NN*H];
__device__ float d_gcn[NN*H];
__device__ float d_Wcomb[LAY*4*HH];
__device__ float d_na[LAY*4];
__device__ float d_ro[(LAY+1)*3];
__device__ int   d_deg[NN];
__device__ int   d_rowptr[NN+1];
__device__ int   d_cursor[NN];
__device__ int   d_csr[NE];
__device__ float d_invdeg[NN];
__device__ float d_invsqrt[NN];
__device__ int   d_bhist[NG];
__device__ int   d_gstart[NG+1];
__device__ float d_gfeat[NG*(LAY+1)*H];
__device__ int   d_btot[NB_SCAN];
__device__ int   d_boff[NB_SCAN];

// ---------------- small prep kernels ----------------------------------------
__global__ void k_zero() {
    int i = blockIdx.x*blockDim.x + threadIdx.x;
    if (i < NN) d_deg[i] = 0;
    if (i < NG) d_bhist[i] = 0;
}

__global__ void k_softmax(const float* __restrict__ lna, const float* __restrict__ lro) {
    if (threadIdx.x == 0) {
        for (int l = 0; l < LAY; l++) {
            float m = -1e30f;
            for (int j = 0; j < 4; j++) m = fmaxf(m, lna[l*4+j]);
            float e[4]; float s = 0.f;
            for (int j = 0; j < 4; j++) { e[j] = expf(lna[l*4+j]-m); s += e[j]; }
            for (int j = 0; j < 4; j++) d_na[l*4+j] = e[j]/s;
        }
        for (int l = 0; l < LAY+1; l++) {
            float m = -1e30f;
            for (int j = 0; j < 3; j++) m = fmaxf(m, lro[l*3+j]);
            float e[3]; float s = 0.f;
            for (int j = 0; j < 3; j++) { e[j] = expf(lro[l*3+j]-m); s += e[j]; }
            for (int j = 0; j < 3; j++) d_ro[l*3+j] = e[j]/s;
        }
    }
}

// Combined per-layer weights (4 effective source matrices):
//   s0 (h)                 : w1*W1 + w2*W3 + w3*W4
//   s1 (sum, scaled invdeg): w1*W2          (= mean path)
//   s2 (sum)               : w2*W3          (= gin path)
//   s3 (gcn_agg)           : w0*W0
__global__ void k_wcomb(const float* __restrict__ Wna) {
    int i = blockIdx.x*blockDim.x + threadIdx.x;
    if (i >= LAY*4*HH) return;
    int l = i/(4*HH); int r = i%(4*HH); int s = r/HH; int e = r%HH;
    const float* W  = Wna + l*5*HH;
    const float* na = d_na + l*4;
    float v;
    if (s == 0)      v = na[1]*W[1*HH+e] + na[2]*W[3*HH+e] + na[3]*W[4*HH+e];
    else if (s == 1) v = na[1]*W[2*HH+e];
    else if (s == 2) v = na[2]*W[3*HH+e];
    else             v = na[0]*W[0*HH+e];
    d_Wcomb[i] = v;
}

__global__ void k_hist(const int* __restrict__ dst, const int* __restrict__ batch) {
    int i = blockIdx.x*blockDim.x + threadIdx.x;
    int stride = gridDim.x*blockDim.x;
    for (int e = i; e < NE; e += stride) atomicAdd(&d_deg[dst[e]], 1);
    for (int n = i; n < NN; n += stride) atomicAdd(&d_bhist[batch[n]], 1);
}

// ---- hierarchical scan for NN ----
__global__ void k_scan1(const int* __restrict__ in, int* __restrict__ out, int n) {
    __shared__ int wsum[32];
    int i = blockIdx.x*1024 + threadIdx.x;
    int lane = threadIdx.x & 31, warp = threadIdx.x >> 5;
    int v = (i < n) ? in[i] : 0;
    int x = v;
    #pragma unroll
    for (int o = 1; o < 32; o <<= 1) {
        int y = __shfl_up_sync(0xffffffffu, x, o);
        if (lane >= o) x += y;
    }
    if (lane == 31) wsum[warp] = x;
    __syncthreads();
    if (warp == 0) {
        int s = wsum[lane];
        #pragma unroll
        for (int o = 1; o < 32; o <<= 1) {
            int y = __shfl_up_sync(0xffffffffu, s, o);
            if (lane >= o) s += y;
        }
        wsum[lane] = s;
    }
    __syncthreads();
    int incl = x + (warp ? wsum[warp-1] : 0);
    if (i < n) out[i] = incl - v;
    if (threadIdx.x == 1023) d_btot[blockIdx.x] = incl;
}

__global__ void k_scan2(int* __restrict__ out, int n, int nb) {
    if (threadIdx.x == 0) {
        int acc = 0;
        for (int b = 0; b < nb; b++) { d_boff[b] = acc; acc += d_btot[b]; }
        out[n] = acc;
    }
}

__global__ void k_scan3(int* __restrict__ out, int n) {
    int i = blockIdx.x*blockDim.x + threadIdx.x;
    if (i < n) out[i] += d_boff[i >> 10];
}

// single-block scan (for NG=512, blockDim=1024)
__global__ void k_scan_small(const int* __restrict__ in, int* __restrict__ out, int n) {
    __shared__ int wsum[32];
    int lane = threadIdx.x & 31, warp = threadIdx.x >> 5;
    int i = threadIdx.x;
    int v = (i < n) ? in[i] : 0;
    int x = v;
    #pragma unroll
    for (int o = 1; o < 32; o <<= 1) {
        int y = __shfl_up_sync(0xffffffffu, x, o);
        if (lane >= o) x += y;
    }
    if (lane == 31) wsum[warp] = x;
    __syncthreads();
    if (warp == 0) {
        int s = wsum[lane];
        #pragma unroll
        for (int o = 1; o < 32; o <<= 1) {
            int y = __shfl_up_sync(0xffffffffu, s, o);
            if (lane >= o) s += y;
        }
        wsum[lane] = s;
    }
    __syncthreads();
    int incl = x + (warp ? wsum[warp-1] : 0);
    if (i < n) out[i] = incl - v;
    if (i == n-1) out[n] = incl;
}

__global__ void k_cursor_stats() {
    int i = blockIdx.x*blockDim.x + threadIdx.x;
    if (i >= NN) return;
    d_cursor[i] = d_rowptr[i];
    int c = d_deg[i];
    float m = (float)(c > 1 ? c : 1);
    d_invdeg[i]  = 1.0f/m;
    d_invsqrt[i] = rsqrtf(m);
}

__global__ void k_scatter(const int* __restrict__ src, const int* __restrict__ dst) {
    int i = blockIdx.x*blockDim.x + threadIdx.x;
    int stride = gridDim.x*blockDim.x;
    for (int e = i; e < NE; e += stride) {
        int d = dst[e];
        int p = atomicAdd(&d_cursor[d], 1);
        d_csr[p] = src[e];
    }
}

// ---------------- aggregation: one warp per dst node, outputs sum + gcn -----
__global__ void k_aggregate(const float* __restrict__ h) {
    int gw   = (blockIdx.x*blockDim.x + threadIdx.x) >> 5;
    int lane = threadIdx.x & 31;
    if (gw >= NN) return;
    int beg = d_rowptr[gw], end = d_rowptr[gw+1];
    const float4* h4 = reinterpret_cast<const float4*>(h);
    float4 s = {0.f,0.f,0.f,0.f};
    float4 g = {0.f,0.f,0.f,0.f};
    for (int e = beg; e < end; e++) {
        int src  = d_csr[e];
        float is = d_invsqrt[src];
        float4 v = h4[src*32 + lane];
        s.x += v.x;    s.y += v.y;    s.z += v.z;    s.w += v.w;
        g.x += v.x*is; g.y += v.y*is; g.z += v.z*is; g.w += v.w*is;
    }
    float isd = d_invsqrt[gw];
    int o = gw*32 + lane;
    reinterpret_cast<float4*>(d_sum)[o] = s;
    float4 gc = {g.x*isd, g.y*isd, g.z*isd, g.w*isd};
    reinterpret_cast<float4*>(d_gcn)[o] = gc;
}

// ---------------- TF32 tensor-core GEMM -------------------------------------
// out[M,128] = sum_s A_s @ W_s  (+bias) (relu)
// BM=128, BN=128, BK=32, 256 threads (8 warps in 4x2), warp tile 32x64
// smem layout: As[m][k] / Bs[n][k] stride 36 -> conflict-free fragment reads

__device__ __forceinline__ uint32_t f2tf32(float f) {
    uint32_t u;
    asm("cvt.rna.tf32.f32 %0, %1;" : "=r"(u) : "f"(f));
    return u;
}

__device__ __forceinline__ void mma_tf32(float* acc,
                                         uint32_t a0, uint32_t a1, uint32_t a2, uint32_t a3,
                                         uint32_t b0, uint32_t b1) {
    asm volatile(
        "mma.sync.aligned.m16n8k8.row.col.f32.tf32.tf32.f32 "
        "{%0,%1,%2,%3}, {%4,%5,%6,%7}, {%8,%9}, {%0,%1,%2,%3};"
        : "+f"(acc[0]), "+f"(acc[1]), "+f"(acc[2]), "+f"(acc[3])
        : "r"(a0), "r"(a1), "r"(a2), "r"(a3), "r"(b0), "r"(b1));
}

__global__ void __launch_bounds__(256)
k_gemm_tf32(const float* __restrict__ A0, const float* __restrict__ A1,
            const float* __restrict__ A2, const float* __restrict__ A3,
            const float* __restrict__ rs1,   // row-scale applied to source 1
            const float* __restrict__ W, const float* __restrict__ bias,
            float* __restrict__ out, int M, int nsrc, int relu)
{
    __shared__ uint32_t As[128][36];
    __shared__ uint32_t Bs[128][36];
    const float* srcs[4] = {A0, A1, A2, A3};
    int tid  = threadIdx.x;
    int lane = tid & 31;
    int wid  = tid >> 5;
    int wm = (wid & 3) * 32;   // warp m offset
    int wn = (wid >> 2) * 64;  // warp n offset
    int lr = lane >> 2, lc = lane & 3;
    int row0 = blockIdx.x * 128;

    float acc[2][8][4];
    #pragma unroll
    for (int mt = 0; mt < 2; mt++)
        #pragma unroll
        for (int nt = 0; nt < 8; nt++)
            #pragma unroll
            for (int c = 0; c < 4; c++) acc[mt][nt][c] = 0.f;

    for (int s = 0; s < nsrc; s++) {
        const float* A  = srcs[s];
        const float* Wb = W + s*HH;
        bool do_scale = (s == 1) && (rs1 != nullptr);
        for (int kt = 0; kt < 4; kt++) {
            int k0 = kt*32;
            // A tile: 128x32 floats = 1024 float4, 4 per thread
            #pragma unroll
            for (int i = 0; i < 4; i++) {
                int idx = tid + i*256;
                int m = idx >> 3, kg = (idx & 7) * 4;
                int r = row0 + m;
                float4 v = {0.f,0.f,0.f,0.f};
                if (r < M) {
                    v = *reinterpret_cast<const float4*>(&A[r*H + k0 + kg]);
                    if (do_scale) {
                        float sc = rs1[r];
                        v.x *= sc; v.y *= sc; v.z *= sc; v.w *= sc;
                    }
                }
                As[m][kg+0] = f2tf32(v.x);
                As[m][kg+1] = f2tf32(v.y);
                As[m][kg+2] = f2tf32(v.z);
                As[m][kg+3] = f2tf32(v.w);
            }
            // B tile: W[(k0+k)*H + n] -> Bs[n][k], 4096 floats, 16 per thread
            #pragma unroll
            for (int i = 0; i < 16; i++) {
                int idx = tid + i*256;
                int k = idx >> 7, n = idx & 127;
                Bs[n][k] = f2tf32(Wb[(k0+k)*H + n]);
            }
            __syncthreads();
            #pragma unroll
            for (int k8 = 0; k8 < 32; k8 += 8) {
                uint32_t bf[8][2];
                #pragma unroll
                for (int nt = 0; nt < 8; nt++) {
                    bf[nt][0] = Bs[wn + nt*8 + lr][k8 + lc];
                    bf[nt][1] = Bs[wn + nt*8 + lr][k8 + 4 + lc];
                }
                #pragma unroll
                for (int mt = 0; mt < 2; mt++) {
                    uint32_t a0 = As[wm + mt*16 + lr    ][k8 + lc];
                    uint32_t a1 = As[wm + mt*16 + 8 + lr][k8 + lc];
                    uint32_t a2 = As[wm + mt*16 + lr    ][k8 + 4 + lc];
                    uint32_t a3 = As[wm + mt*16 + 8 + lr][k8 + 4 + lc];
                    #pragma unroll
                    for (int nt = 0; nt < 8; nt++)
                        mma_tf32(acc[mt][nt], a0, a1, a2, a3, bf[nt][0], bf[nt][1]);
                }
            }
            __syncthreads();
        }
    }
    // epilogue
    #pragma unroll
    for (int mt = 0; mt < 2; mt++) {
        int r0 = row0 + wm + mt*16 + lr;
        int r1 = r0 + 8;
        #pragma unroll
        for (int nt = 0; nt < 8; nt++) {
            int c = wn + nt*8 + 2*lc;
            float b0 = bias ? bias[c]   : 0.f;
            float b1 = bias ? bias[c+1] : 0.f;
            float v0 = acc[mt][nt][0] + b0;
            float v1 = acc[mt][nt][1] + b1;
            float v2 = acc[mt][nt][2] + b0;
            float v3 = acc[mt][nt][3] + b1;
            if (relu) {
                v0 = fmaxf(v0, 0.f); v1 = fmaxf(v1, 0.f);
                v2 = fmaxf(v2, 0.f); v3 = fmaxf(v3, 0.f);
            }
            if (r0 < M) { out[r0*H + c] = v0; out[r0*H + c + 1] = v1; }
            if (r1 < M) { out[r1*H + c] = v2; out[r1*H + c + 1] = v3; }
        }
    }
}

// ---------------- readout: one block per graph, one thread per column -------
__global__ void k_readout(const float* __restrict__ h, int layer) {
    int gr = blockIdx.x;
    int c  = threadIdx.x;
    int beg = d_gstart[gr], end = d_gstart[gr+1];
    float s = 0.f, mx = -3.4e38f;
    for (int n = beg; n < end; n++) {
        float v = h[n*H + c];
        s += v;
        mx = fmaxf(mx, v);
    }
    int cnt = end - beg;
    float mean = s / (float)(cnt > 1 ? cnt : 1);
    if (cnt == 0) mx = 0.f;
    const float* w = d_ro + layer*3;
    d_gfeat[gr*((LAY+1)*H) + layer*H + c] = w[0]*mean + w[1]*mx + w[2]*s;
}

// ---------------- head: relu(g @ Wl + bl) @ Wc + bc -------------------------
__global__ void k_head(const float* __restrict__ Wl, const float* __restrict__ bl,
                       const float* __restrict__ Wc, const float* __restrict__ bc,
                       float* __restrict__ out) {
    __shared__ float sg[(LAY+1)*H];
    __shared__ float mid[H];
    int gr = blockIdx.x;
    int t  = threadIdx.x;
    for (int i = t; i < (LAY+1)*H; i += H) sg[i] = d_gfeat[gr*((LAY+1)*H) + i];
    __syncthreads();
    float acc = bl[t];
    for (int k = 0; k < (LAY+1)*H; k++) acc += sg[k]*Wl[k*H + t];
    mid[t] = fmaxf(acc, 0.f);
    __syncthreads();
    if (t < NOUT) {
        float a = bc[t];
        for (int k = 0; k < H; k++) a += mid[k]*Wc[k*NOUT + t];
        out[gr*NOUT + t] = a;
    }
}

// ---------------- launch ----------------------------------------------------
extern "C" void kernel_launch(void* const* d_in, const int* in_sizes, int n_in,
                              void* d_out, int out_size) {
    const float* x      = (const float*)d_in[0];
    const int*   ei     = (const int*)  d_in[1];
    const int*   batch  = (const int*)  d_in[2];
    const float* lin1_W = (const float*)d_in[3];
    const float* lin1_b = (const float*)d_in[4];
    const float* Wna    = (const float*)d_in[5];
    const float* lna    = (const float*)d_in[6];
    const float* lro    = (const float*)d_in[7];
    const float* lout_W = (const float*)d_in[8];
    const float* lout_b = (const float*)d_in[9];
    const float* cls_W  = (const float*)d_in[10];
    const float* cls_b  = (const float*)d_in[11];
    const int* srcp = ei;
    const int* dstp = ei + NE;

    float *hA, *hB, *psum, *pgcn, *pWcomb, *pinvdeg;
    int *pdeg, *prowptr, *pbhist, *pgstart;
    cudaGetSymbolAddress((void**)&hA,      d_hA);
    cudaGetSymbolAddress((void**)&hB,      d_hB);
    cudaGetSymbolAddress((void**)&psum,    d_sum);
    cudaGetSymbolAddress((void**)&pgcn,    d_gcn);
    cudaGetSymbolAddress((void**)&pWcomb,  d_Wcomb);
    cudaGetSymbolAddress((void**)&pinvdeg, d_invdeg);
    cudaGetSymbolAddress((void**)&pdeg,    d_deg);
    cudaGetSymbolAddress((void**)&prowptr, d_rowptr);
    cudaGetSymbolAddress((void**)&pbhist,  d_bhist);
    cudaGetSymbolAddress((void**)&pgstart, d_gstart);

    k_zero<<<(NN+255)/256, 256>>>();
    k_softmax<<<1, 32>>>(lna, lro);
    k_wcomb<<<(LAY*4*HH+255)/256, 256>>>(Wna);
    k_hist<<<1024, 256>>>(dstp, batch);
    k_scan1<<<NB_SCAN, 1024>>>(pdeg, prowptr, NN);
    k_scan2<<<1, 32>>>(prowptr, NN, NB_SCAN);
    k_scan3<<<NB_SCAN, 1024>>>(prowptr, NN);
    k_scan_small<<<1, 1024>>>(pbhist, pgstart, NG);
    k_cursor_stats<<<(NN+255)/256, 256>>>();
    k_scatter<<<1024, 256>>>(srcp, dstp);

    int gblocks = (NN + 127) / 128;
    // h = x @ lin1_W + b
    k_gemm_tf32<<<gblocks, 256>>>(x, x, x, x, nullptr, lin1_W, lin1_b, hA, NN, 1, 0);
    k_readout<<<NG, H>>>(hA, 0);

    float* cur = hA;
    float* nxt = hB;
    for (int l = 0; l < LAY; l++) {
        k_aggregate<<<(NN*32+255)/256, 256>>>(cur);
        // sources: h, sum*invdeg (mean), sum, gcn
        k_gemm_tf32<<<gblocks, 256>>>(cur, psum, psum, pgcn, pinvdeg,
                                      pWcomb + l*4*HH, nullptr, nxt, NN, 4, 1);
        k_readout<<<NG, H>>>(nxt, l+1);
        float* t = cur; cur = nxt; nxt = t;
    }
    k_head<<<NG, H>>>(lout_W, lout_b, cls_W, cls_b, (float*)d_out);
}

// round 5
// speedup vs baseline: 3.5609x; 1.4736x over previous
#include <cuda_runtime.h>
#include <math.h>
#include <stdint.h>

#define NN 50000
#define NE 800000
#define H 128
#define LAY 3
#define NG 512
#define NOUT 10
#define HH (H*H)
#define NB_SCAN ((NN + 1023) / 1024)
#define NWMAT (LAY*4 + 1)          // 12 combined + 1 lin1
#define SM_STRIDE 36               // floats; 144B, 16B-aligned, conflict-free
#define STAGE_ELEMS (128*SM_STRIDE)
#define GEMM_SMEM (4*STAGE_ELEMS*4)  // As[2]+Bs[2], bytes = 73728

// ---------------- scratch (static device globals) ---------------------------
__device__ float    d_hA[NN*H];
__device__ float    d_hB[NN*H];
__device__ float    d_sum[NN*H];
__device__ float    d_gcn[NN*H];
__device__ uint32_t d_Wt[NWMAT*HH];   // tf32, [mat][n][k]
__device__ float    d_na[LAY*4];
__device__ float    d_ro[(LAY+1)*3];
__device__ int      d_deg[NN];
__device__ int      d_rowptr[NN+1];
__device__ int      d_cursor[NN];
__device__ int      d_csr[NE];
__device__ float    d_invdeg[NN];
__device__ float    d_invsqrt[NN];
__device__ int      d_bhist[NG];
__device__ int      d_gstart[NG+1];
__device__ float    d_gfeat[NG*(LAY+1)*H];
__device__ int      d_btot[NB_SCAN];
__device__ int      d_boff[NB_SCAN];

// ---------------- helpers ----------------------------------------------------
__device__ __forceinline__ uint32_t f2tf32(float f) {
    uint32_t u;
    asm("cvt.rna.tf32.f32 %0, %1;" : "=r"(u) : "f"(f));
    return u;
}

__device__ __forceinline__ void cp16(uint32_t dst, const void* src, int sz) {
    asm volatile("cp.async.ca.shared.global [%0], [%1], 16, %2;"
                 :: "r"(dst), "l"(src), "r"(sz));
}
__device__ __forceinline__ void cp_commit() {
    asm volatile("cp.async.commit_group;");
}
template<int N>
__device__ __forceinline__ void cp_wait() {
    asm volatile("cp.async.wait_group %0;" :: "n"(N));
}

__device__ __forceinline__ void mma_tf32(float* acc,
                                         uint32_t a0, uint32_t a1, uint32_t a2, uint32_t a3,
                                         uint32_t b0, uint32_t b1) {
    asm volatile(
        "mma.sync.aligned.m16n8k8.row.col.f32.tf32.tf32.f32 "
        "{%0,%1,%2,%3}, {%4,%5,%6,%7}, {%8,%9}, {%0,%1,%2,%3};"
        : "+f"(acc[0]), "+f"(acc[1]), "+f"(acc[2]), "+f"(acc[3])
        : "r"(a0), "r"(a1), "r"(a2), "r"(a3), "r"(b0), "r"(b1));
}

// ---------------- init: zero counters + alpha softmaxes ----------------------
__global__ void k_init(const float* __restrict__ lna, const float* __restrict__ lro) {
    int i = blockIdx.x*blockDim.x + threadIdx.x;
    if (i < NN) d_deg[i] = 0;
    if (i < NG) d_bhist[i] = 0;
    if (i == 0) {
        for (int l = 0; l < LAY; l++) {
            float m = -1e30f;
            for (int j = 0; j < 4; j++) m = fmaxf(m, lna[l*4+j]);
            float e[4]; float s = 0.f;
            for (int j = 0; j < 4; j++) { e[j] = expf(lna[l*4+j]-m); s += e[j]; }
            for (int j = 0; j < 4; j++) d_na[l*4+j] = e[j]/s;
        }
        for (int l = 0; l < LAY+1; l++) {
            float m = -1e30f;
            for (int j = 0; j < 3; j++) m = fmaxf(m, lro[l*3+j]);
            float e[3]; float s = 0.f;
            for (int j = 0; j < 3; j++) { e[j] = expf(lro[l*3+j]-m); s += e[j]; }
            for (int j = 0; j < 3; j++) d_ro[l*3+j] = e[j]/s;
        }
    }
}

// Combined per-layer weights, tf32, transposed to [mat][n][k]:
//   s0 (h)                 : w1*W1 + w2*W3 + w3*W4
//   s1 (sum * invdeg)      : w1*W2
//   s2 (sum)               : w2*W3
//   s3 (gcn_agg)           : w0*W0
//   mat 12                 : lin1_W
__global__ void k_wcomb(const float* __restrict__ Wna, const float* __restrict__ lin1_W) {
    int i = blockIdx.x*blockDim.x + threadIdx.x;
    if (i >= NWMAT*HH) return;
    int mat = i/HH; int e = i%HH;
    int k = e >> 7, n = e & 127;     // read coalesced over n
    float v;
    if (mat < LAY*4) {
        int l = mat >> 2, s = mat & 3;
        const float* W  = Wna + l*5*HH;
        const float* na = d_na + l*4;
        int idx = k*H + n;
        if (s == 0)      v = na[1]*W[1*HH+idx] + na[2]*W[3*HH+idx] + na[3]*W[4*HH+idx];
        else if (s == 1) v = na[1]*W[2*HH+idx];
        else if (s == 2) v = na[2]*W[3*HH+idx];
        else             v = na[0]*W[0*HH+idx];
    } else {
        v = lin1_W[k*H + n];
    }
    d_Wt[mat*HH + n*H + k] = f2tf32(v);
}

__global__ void k_hist(const int* __restrict__ dst, const int* __restrict__ batch) {
    int i = blockIdx.x*blockDim.x + threadIdx.x;
    int stride = gridDim.x*blockDim.x;
    for (int e = i; e < NE; e += stride) atomicAdd(&d_deg[dst[e]], 1);
    for (int n = i; n < NN; n += stride) atomicAdd(&d_bhist[batch[n]], 1);
}

// ---- hierarchical scan for NN ----
__global__ void k_scan1(const int* __restrict__ in, int* __restrict__ out, int n) {
    __shared__ int wsum[32];
    int i = blockIdx.x*1024 + threadIdx.x;
    int lane = threadIdx.x & 31, warp = threadIdx.x >> 5;
    int v = (i < n) ? in[i] : 0;
    int x = v;
    #pragma unroll
    for (int o = 1; o < 32; o <<= 1) {
        int y = __shfl_up_sync(0xffffffffu, x, o);
        if (lane >= o) x += y;
    }
    if (lane == 31) wsum[warp] = x;
    __syncthreads();
    if (warp == 0) {
        int s = wsum[lane];
        #pragma unroll
        for (int o = 1; o < 32; o <<= 1) {
            int y = __shfl_up_sync(0xffffffffu, s, o);
            if (lane >= o) s += y;
        }
        wsum[lane] = s;
    }
    __syncthreads();
    int incl = x + (warp ? wsum[warp-1] : 0);
    if (i < n) out[i] = incl - v;
    if (threadIdx.x == 1023) d_btot[blockIdx.x] = incl;
}

__global__ void k_scan2(int* __restrict__ out, int n, int nb) {
    if (threadIdx.x == 0) {
        int acc = 0;
        for (int b = 0; b < nb; b++) { d_boff[b] = acc; acc += d_btot[b]; }
        out[n] = acc;
    }
}

// add block offsets; also init cursor + degree stats (fused)
__global__ void k_scan3c(int* __restrict__ out, int n) {
    int i = blockIdx.x*blockDim.x + threadIdx.x;
    if (i >= n) return;
    int v = out[i] + d_boff[i >> 10];
    out[i] = v;
    d_cursor[i] = v;
    int c = d_deg[i];
    float m = (float)(c > 1 ? c : 1);
    d_invdeg[i]  = 1.0f/m;
    d_invsqrt[i] = rsqrtf(m);
}

// single-block scan (for NG=512, blockDim=1024)
__global__ void k_scan_small(const int* __restrict__ in, int* __restrict__ out, int n) {
    __shared__ int wsum[32];
    int lane = threadIdx.x & 31, warp = threadIdx.x >> 5;
    int i = threadIdx.x;
    int v = (i < n) ? in[i] : 0;
    int x = v;
    #pragma unroll
    for (int o = 1; o < 32; o <<= 1) {
        int y = __shfl_up_sync(0xffffffffu, x, o);
        if (lane >= o) x += y;
    }
    if (lane == 31) wsum[warp] = x;
    __syncthreads();
    if (warp == 0) {
        int s = wsum[lane];
        #pragma unroll
        for (int o = 1; o < 32; o <<= 1) {
            int y = __shfl_up_sync(0xffffffffu, s, o);
            if (lane >= o) s += y;
        }
        wsum[lane] = s;
    }
    __syncthreads();
    int incl = x + (warp ? wsum[warp-1] : 0);
    if (i < n) out[i] = incl - v;
    if (i == n-1) out[n] = incl;
}

__global__ void k_scatter(const int* __restrict__ src, const int* __restrict__ dst) {
    int i = blockIdx.x*blockDim.x + threadIdx.x;
    int stride = gridDim.x*blockDim.x;
    for (int e = i; e < NE; e += stride) {
        int d = dst[e];
        int p = atomicAdd(&d_cursor[d], 1);
        d_csr[p] = src[e];
    }
}

// ---------------- aggregation: one warp per dst node, outputs sum + gcn -----
__global__ void k_aggregate(const float* __restrict__ h) {
    int gw   = (blockIdx.x*blockDim.x + threadIdx.x) >> 5;
    int lane = threadIdx.x & 31;
    if (gw >= NN) return;
    int beg = d_rowptr[gw], end = d_rowptr[gw+1];
    const float4* h4 = reinterpret_cast<const float4*>(h);
    float4 s = {0.f,0.f,0.f,0.f};
    float4 g = {0.f,0.f,0.f,0.f};
    for (int e = beg; e < end; e++) {
        int src  = d_csr[e];
        float is = d_invsqrt[src];
        float4 v = h4[src*32 + lane];
        s.x += v.x;    s.y += v.y;    s.z += v.z;    s.w += v.w;
        g.x += v.x*is; g.y += v.y*is; g.z += v.z*is; g.w += v.w*is;
    }
    float isd = d_invsqrt[gw];
    int o = gw*32 + lane;
    reinterpret_cast<float4*>(d_sum)[o] = s;
    float4 gc = {g.x*isd, g.y*isd, g.z*isd, g.w*isd};
    reinterpret_cast<float4*>(d_gcn)[o] = gc;
}

// ---------------- pipelined TF32 tensor-core GEMM ----------------------------
// out[M,128] = sum_s A_s @ W_s  (+bias) (relu)
// BM=128, BN=128, BK=32 chunks over flattened (source, kt); 2-stage cp.async.
// A staged as raw f32 (converted+optionally row-scaled at fragment load).
// B pre-converted tf32 [n][k] in d_Wt.
__global__ void __launch_bounds__(256)
k_gemm_pipe(const float* __restrict__ A0, const float* __restrict__ A1,
            const float* __restrict__ A2, const float* __restrict__ A3,
            const float* __restrict__ rs1,      // row scale for source 1 (or null)
            const uint32_t* __restrict__ Wt,    // [nsrc][128][128] tf32 n-major
            const float* __restrict__ bias,
            float* __restrict__ out, int M, int nsrc, int relu)
{
    extern __shared__ char smem[];
    float*    AsF = (float*)smem;                          // [2][STAGE_ELEMS]
    uint32_t* BsU = (uint32_t*)(smem + 2*STAGE_ELEMS*4);   // [2][STAGE_ELEMS]
    uint32_t asAddr = (uint32_t)__cvta_generic_to_shared(AsF);
    uint32_t bsAddr = (uint32_t)__cvta_generic_to_shared(BsU);

    const float* srcs[4] = {A0, A1, A2, A3};
    int tid  = threadIdx.x;
    int lane = tid & 31;
    int wid  = tid >> 5;
    int wm = (wid & 3) * 32;
    int wn = (wid >> 2) * 64;
    int lr = lane >> 2, lc = lane & 3;
    int row0 = blockIdx.x * 128;

    // preload mean-path row scales for this thread's fragment rows
    float inv_a[2][2];
    #pragma unroll
    for (int mt = 0; mt < 2; mt++) {
        int r0 = row0 + wm + mt*16 + lr;
        int r1 = r0 + 8;
        inv_a[mt][0] = (rs1 && r0 < M) ? rs1[r0] : 1.f;
        inv_a[mt][1] = (rs1 && r1 < M) ? rs1[r1] : 1.f;
    }

    float acc[2][8][4];
    #pragma unroll
    for (int mt = 0; mt < 2; mt++)
        #pragma unroll
        for (int nt = 0; nt < 8; nt++)
            #pragma unroll
            for (int c = 0; c < 4; c++) acc[mt][nt][c] = 0.f;

    const int C = nsrc * 4;

    auto issue = [&](int c) {
        int st = c & 1;
        int s  = c >> 2;
        int k0 = (c & 3) * 32;
        const float*    A  = srcs[s];
        const uint32_t* Wb = Wt + s*HH;
        #pragma unroll
        for (int i = 0; i < 4; i++) {
            int idx = tid + i*256;
            int m = idx >> 3, kg = (idx & 7) * 4;
            int r = row0 + m;
            const float* src = A + (size_t)(r < M ? r : 0)*H + k0 + kg;
            cp16(asAddr + (st*STAGE_ELEMS + m*SM_STRIDE + kg)*4, src, (r < M) ? 16 : 0);
        }
        #pragma unroll
        for (int i = 0; i < 4; i++) {
            int idx = tid + i*256;
            int n = idx >> 3, kg = (idx & 7) * 4;
            cp16(bsAddr + (st*STAGE_ELEMS + n*SM_STRIDE + kg)*4, Wb + n*H + k0 + kg, 16);
        }
        cp_commit();
    };

    issue(0);
    for (int c = 0; c < C; c++) {
        if (c + 1 < C) { issue(c + 1); cp_wait<1>(); }
        else           { cp_wait<0>(); }
        __syncthreads();

        int st = c & 1;
        int s  = c >> 2;
        bool dosc = (s == 1) && (rs1 != nullptr);
        const float*    Ab = AsF + st*STAGE_ELEMS;
        const uint32_t* Bb = BsU + st*STAGE_ELEMS;

        #pragma unroll
        for (int k8 = 0; k8 < 32; k8 += 8) {
            uint32_t bf[8][2];
            #pragma unroll
            for (int nt = 0; nt < 8; nt++) {
                int nrow = wn + nt*8 + lr;
                bf[nt][0] = Bb[nrow*SM_STRIDE + k8 + lc];
                bf[nt][1] = Bb[nrow*SM_STRIDE + k8 + 4 + lc];
            }
            #pragma unroll
            for (int mt = 0; mt < 2; mt++) {
                int m0 = wm + mt*16 + lr;
                float f0 = Ab[m0*SM_STRIDE + k8 + lc];
                float f1 = Ab[(m0+8)*SM_STRIDE + k8 + lc];
                float f2 = Ab[m0*SM_STRIDE + k8 + 4 + lc];
                float f3 = Ab[(m0+8)*SM_STRIDE + k8 + 4 + lc];
                if (dosc) {
                    f0 *= inv_a[mt][0]; f2 *= inv_a[mt][0];
                    f1 *= inv_a[mt][1]; f3 *= inv_a[mt][1];
                }
                uint32_t a0 = f2tf32(f0), a1 = f2tf32(f1);
                uint32_t a2 = f2tf32(f2), a3 = f2tf32(f3);
                #pragma unroll
                for (int nt = 0; nt < 8; nt++)
                    mma_tf32(acc[mt][nt], a0, a1, a2, a3, bf[nt][0], bf[nt][1]);
            }
        }
        __syncthreads();
    }

    // epilogue
    #pragma unroll
    for (int mt = 0; mt < 2; mt++) {
        int r0 = row0 + wm + mt*16 + lr;
        int r1 = r0 + 8;
        #pragma unroll
        for (int nt = 0; nt < 8; nt++) {
            int c = wn + nt*8 + 2*lc;
            float b0 = bias ? bias[c]   : 0.f;
            float b1 = bias ? bias[c+1] : 0.f;
            float v0 = acc[mt][nt][0] + b0;
            float v1 = acc[mt][nt][1] + b1;
            float v2 = acc[mt][nt][2] + b0;
            float v3 = acc[mt][nt][3] + b1;
            if (relu) {
                v0 = fmaxf(v0, 0.f); v1 = fmaxf(v1, 0.f);
                v2 = fmaxf(v2, 0.f); v3 = fmaxf(v3, 0.f);
            }
            if (r0 < M) { out[r0*H + c] = v0; out[r0*H + c + 1] = v1; }
            if (r1 < M) { out[r1*H + c] = v2; out[r1*H + c + 1] = v3; }
        }
    }
}

// ---------------- readout: one block per graph, one thread per column -------
__global__ void k_readout(const float* __restrict__ h, int layer) {
    int gr = blockIdx.x;
    int c  = threadIdx.x;
    int beg = d_gstart[gr], end = d_gstart[gr+1];
    float s = 0.f, mx = -3.4e38f;
    for (int n = beg; n < end; n++) {
        float v = h[n*H + c];
        s += v;
        mx = fmaxf(mx, v);
    }
    int cnt = end - beg;
    float mean = s / (float)(cnt > 1 ? cnt : 1);
    if (cnt == 0) mx = 0.f;
    const float* w = d_ro + layer*3;
    d_gfeat[gr*((LAY+1)*H) + layer*H + c] = w[0]*mean + w[1]*mx + w[2]*s;
}

// ---------------- head: relu(g @ Wl + bl) @ Wc + bc -------------------------
__global__ void k_head(const float* __restrict__ Wl, const float* __restrict__ bl,
                       const float* __restrict__ Wc, const float* __restrict__ bc,
                       float* __restrict__ out) {
    __shared__ float sg[(LAY+1)*H];
    __shared__ float mid[H];
    int gr = blockIdx.x;
    int t  = threadIdx.x;
    for (int i = t; i < (LAY+1)*H; i += H) sg[i] = d_gfeat[gr*((LAY+1)*H) + i];
    __syncthreads();
    float acc = bl[t];
    for (int k = 0; k < (LAY+1)*H; k++) acc += sg[k]*Wl[k*H + t];
    mid[t] = fmaxf(acc, 0.f);
    __syncthreads();
    if (t < NOUT) {
        float a = bc[t];
        for (int k = 0; k < H; k++) a += mid[k]*Wc[k*NOUT + t];
        out[gr*NOUT + t] = a;
    }
}

// ---------------- launch ----------------------------------------------------
extern "C" void kernel_launch(void* const* d_in, const int* in_sizes, int n_in,
                              void* d_out, int out_size) {
    const float* x      = (const float*)d_in[0];
    const int*   ei     = (const int*)  d_in[1];
    const int*   batch  = (const int*)  d_in[2];
    const float* lin1_W = (const float*)d_in[3];
    const float* lin1_b = (const float*)d_in[4];
    const float* Wna    = (const float*)d_in[5];
    const float* lna    = (const float*)d_in[6];
    const float* lro    = (const float*)d_in[7];
    const float* lout_W = (const float*)d_in[8];
    const float* lout_b = (const float*)d_in[9];
    const float* cls_W  = (const float*)d_in[10];
    const float* cls_b  = (const float*)d_in[11];
    const int* srcp = ei;
    const int* dstp = ei + NE;

    float *hA, *hB, *psum, *pgcn, *pinvdeg;
    uint32_t* pWt;
    int *pdeg, *prowptr, *pbhist, *pgstart;
    cudaGetSymbolAddress((void**)&hA,      d_hA);
    cudaGetSymbolAddress((void**)&hB,      d_hB);
    cudaGetSymbolAddress((void**)&psum,    d_sum);
    cudaGetSymbolAddress((void**)&pgcn,    d_gcn);
    cudaGetSymbolAddress((void**)&pWt,     d_Wt);
    cudaGetSymbolAddress((void**)&pinvdeg, d_invdeg);
    cudaGetSymbolAddress((void**)&pdeg,    d_deg);
    cudaGetSymbolAddress((void**)&prowptr, d_rowptr);
    cudaGetSymbolAddress((void**)&pbhist,  d_bhist);
    cudaGetSymbolAddress((void**)&pgstart, d_gstart);

    cudaFuncSetAttribute(k_gemm_pipe,
                         cudaFuncAttributeMaxDynamicSharedMemorySize, GEMM_SMEM);

    k_init<<<(NN+255)/256, 256>>>(lna, lro);
    k_wcomb<<<(NWMAT*HH+255)/256, 256>>>(Wna, lin1_W);
    k_hist<<<1024, 256>>>(dstp, batch);
    k_scan1<<<NB_SCAN, 1024>>>(pdeg, prowptr, NN);
    k_scan2<<<1, 32>>>(prowptr, NN, NB_SCAN);
    k_scan3c<<<NB_SCAN, 1024>>>(prowptr, NN);
    k_scan_small<<<1, 1024>>>(pbhist, pgstart, NG);
    k_scatter<<<1024, 256>>>(srcp, dstp);

    int gblocks = (NN + 127) / 128;
    // h = x @ lin1_W + b   (lin1 weights live in slot LAY*4 of d_Wt)
    k_gemm_pipe<<<gblocks, 256, GEMM_SMEM>>>(x, x, x, x, nullptr,
                                             pWt + (LAY*4)*HH, lin1_b, hA, NN, 1, 0);
    k_readout<<<NG, H>>>(hA, 0);

    float* cur = hA;
    float* nxt = hB;
    for (int l = 0; l < LAY; l++) {
        k_aggregate<<<(NN*32+255)/256, 256>>>(cur);
        // sources: h, sum*invdeg (mean), sum, gcn
        k_gemm_pipe<<<gblocks, 256, GEMM_SMEM>>>(cur, psum, psum, pgcn, pinvdeg,
                                                 pWt + l*4*HH, nullptr, nxt, NN, 4, 1);
        k_readout<<<NG, H>>>(nxt, l+1);
        float* t = cur; cur = nxt; nxt = t;
    }
    k_head<<<NG, H>>>(lout_W, lout_b, cls_W, cls_b, (float*)d_out);
}

// round 6
// speedup vs baseline: 3.5658x; 1.0014x over previous
#include <cuda_runtime.h>
#include <cuda_fp16.h>
#include <math.h>
#include <stdint.h>

#define NN 50000
#define NE 800000
#define H 128
#define LAY 3
#define NG 512
#define NOUT 10
#define HH (H*H)
#define NB_SCAN ((NN + 1023) / 1024)
#define NWMAT (LAY*4 + 1)          // 12 combined + 1 lin1
#define SM_STRIDE 36               // floats; 144B, 16B-aligned, conflict-free
#define STAGE_ELEMS (128*SM_STRIDE)
#define GEMM_SMEM (4*STAGE_ELEMS*4)  // As[2]+Bs[2], bytes = 73728

// ---------------- scratch (static device globals) ---------------------------
__device__ float    d_hA[NN*H];
__device__ float    d_hB[NN*H];
__device__ __half   d_h16A[NN*H];
__device__ __half   d_h16B[NN*H];
__device__ float    d_sum[NN*H];
__device__ float    d_gcn[NN*H];
__device__ uint32_t d_Wt[NWMAT*HH];   // tf32, [mat][n][k]
__device__ float    d_na[LAY*4];
__device__ float    d_ro[(LAY+1)*3];
__device__ int      d_deg[NN];
__device__ int      d_rowptr[NN+1];
__device__ int      d_cursor[NN];
__device__ int      d_csr[NE];
__device__ float    d_invdeg[NN];
__device__ float    d_invsqrt[NN];
__device__ int      d_bhist[NG];
__device__ int      d_gstart[NG+1];
__device__ float    d_gfeat[NG*(LAY+1)*H];
__device__ int      d_btot[NB_SCAN];
__device__ int      d_boff[NB_SCAN];

// ---------------- helpers ----------------------------------------------------
__device__ __forceinline__ uint32_t f2tf32(float f) {
    uint32_t u;
    asm("cvt.rna.tf32.f32 %0, %1;" : "=r"(u) : "f"(f));
    return u;
}

__device__ __forceinline__ void cp16(uint32_t dst, const void* src, int sz) {
    asm volatile("cp.async.ca.shared.global [%0], [%1], 16, %2;"
                 :: "r"(dst), "l"(src), "r"(sz));
}
__device__ __forceinline__ void cp_commit() {
    asm volatile("cp.async.commit_group;");
}
template<int N>
__device__ __forceinline__ void cp_wait() {
    asm volatile("cp.async.wait_group %0;" :: "n"(N));
}

__device__ __forceinline__ void mma_tf32(float* acc,
                                         uint32_t a0, uint32_t a1, uint32_t a2, uint32_t a3,
                                         uint32_t b0, uint32_t b1) {
    asm volatile(
        "mma.sync.aligned.m16n8k8.row.col.f32.tf32.tf32.f32 "
        "{%0,%1,%2,%3}, {%4,%5,%6,%7}, {%8,%9}, {%0,%1,%2,%3};"
        : "+f"(acc[0]), "+f"(acc[1]), "+f"(acc[2]), "+f"(acc[3])
        : "r"(a0), "r"(a1), "r"(a2), "r"(a3), "r"(b0), "r"(b1));
}

// ---------------- init: zero counters + alpha softmaxes ----------------------
__global__ void k_init(const float* __restrict__ lna, const float* __restrict__ lro) {
    int i = blockIdx.x*blockDim.x + threadIdx.x;
    if (i < NN) d_deg[i] = 0;
    if (i < NG) d_bhist[i] = 0;
    if (i == 0) {
        for (int l = 0; l < LAY; l++) {
            float m = -1e30f;
            for (int j = 0; j < 4; j++) m = fmaxf(m, lna[l*4+j]);
            float e[4]; float s = 0.f;
            for (int j = 0; j < 4; j++) { e[j] = expf(lna[l*4+j]-m); s += e[j]; }
            for (int j = 0; j < 4; j++) d_na[l*4+j] = e[j]/s;
        }
        for (int l = 0; l < LAY+1; l++) {
            float m = -1e30f;
            for (int j = 0; j < 3; j++) m = fmaxf(m, lro[l*3+j]);
            float e[3]; float s = 0.f;
            for (int j = 0; j < 3; j++) { e[j] = expf(lro[l*3+j]-m); s += e[j]; }
            for (int j = 0; j < 3; j++) d_ro[l*3+j] = e[j]/s;
        }
    }
}

// Combined per-layer weights, tf32, transposed to [mat][n][k]:
//   s0 (h)            : w1*W1 + w2*W3 + w3*W4
//   s1 (sum * invdeg) : w1*W2
//   s2 (sum)          : w2*W3
//   s3 (gcn_agg)      : w0*W0
//   mat 12            : lin1_W
__global__ void k_wcomb(const float* __restrict__ Wna, const float* __restrict__ lin1_W) {
    int i = blockIdx.x*blockDim.x + threadIdx.x;
    if (i >= NWMAT*HH) return;
    int mat = i/HH; int e = i%HH;
    int k = e >> 7, n = e & 127;
    float v;
    if (mat < LAY*4) {
        int l = mat >> 2, s = mat & 3;
        const float* W  = Wna + l*5*HH;
        const float* na = d_na + l*4;
        int idx = k*H + n;
        if (s == 0)      v = na[1]*W[1*HH+idx] + na[2]*W[3*HH+idx] + na[3]*W[4*HH+idx];
        else if (s == 1) v = na[1]*W[2*HH+idx];
        else if (s == 2) v = na[2]*W[3*HH+idx];
        else             v = na[0]*W[0*HH+idx];
    } else {
        v = lin1_W[k*H + n];
    }
    d_Wt[mat*HH + n*H + k] = f2tf32(v);
}

__global__ void k_hist(const int* __restrict__ dst, const int* __restrict__ batch) {
    int i = blockIdx.x*blockDim.x + threadIdx.x;
    int stride = gridDim.x*blockDim.x;
    for (int e = i; e < NE; e += stride) atomicAdd(&d_deg[dst[e]], 1);
    for (int n = i; n < NN; n += stride) atomicAdd(&d_bhist[batch[n]], 1);
}

// ---- hierarchical scan for NN ----
__global__ void k_scan1(const int* __restrict__ in, int* __restrict__ out, int n) {
    __shared__ int wsum[32];
    int i = blockIdx.x*1024 + threadIdx.x;
    int lane = threadIdx.x & 31, warp = threadIdx.x >> 5;
    int v = (i < n) ? in[i] : 0;
    int x = v;
    #pragma unroll
    for (int o = 1; o < 32; o <<= 1) {
        int y = __shfl_up_sync(0xffffffffu, x, o);
        if (lane >= o) x += y;
    }
    if (lane == 31) wsum[warp] = x;
    __syncthreads();
    if (warp == 0) {
        int s = wsum[lane];
        #pragma unroll
        for (int o = 1; o < 32; o <<= 1) {
            int y = __shfl_up_sync(0xffffffffu, s, o);
            if (lane >= o) s += y;
        }
        wsum[lane] = s;
    }
    __syncthreads();
    int incl = x + (warp ? wsum[warp-1] : 0);
    if (i < n) out[i] = incl - v;
    if (threadIdx.x == 1023) d_btot[blockIdx.x] = incl;
}

__global__ void k_scan2(int* __restrict__ out, int n, int nb) {
    if (threadIdx.x == 0) {
        int acc = 0;
        for (int b = 0; b < nb; b++) { d_boff[b] = acc; acc += d_btot[b]; }
        out[n] = acc;
    }
}

// add block offsets; also init cursor + degree stats (fused)
__global__ void k_scan3c(int* __restrict__ out, int n) {
    int i = blockIdx.x*blockDim.x + threadIdx.x;
    if (i >= n) return;
    int v = out[i] + d_boff[i >> 10];
    out[i] = v;
    d_cursor[i] = v;
    int c = d_deg[i];
    float m = (float)(c > 1 ? c : 1);
    d_invdeg[i]  = 1.0f/m;
    d_invsqrt[i] = rsqrtf(m);
}

// single-block scan (for NG=512, blockDim=1024)
__global__ void k_scan_small(const int* __restrict__ in, int* __restrict__ out, int n) {
    __shared__ int wsum[32];
    int lane = threadIdx.x & 31, warp = threadIdx.x >> 5;
    int i = threadIdx.x;
    int v = (i < n) ? in[i] : 0;
    int x = v;
    #pragma unroll
    for (int o = 1; o < 32; o <<= 1) {
        int y = __shfl_up_sync(0xffffffffu, x, o);
        if (lane >= o) x += y;
    }
    if (lane == 31) wsum[warp] = x;
    __syncthreads();
    if (warp == 0) {
        int s = wsum[lane];
        #pragma unroll
        for (int o = 1; o < 32; o <<= 1) {
            int y = __shfl_up_sync(0xffffffffu, s, o);
            if (lane >= o) s += y;
        }
        wsum[lane] = s;
    }
    __syncthreads();
    int incl = x + (warp ? wsum[warp-1] : 0);
    if (i < n) out[i] = incl - v;
    if (i == n-1) out[n] = incl;
}

__global__ void k_scatter(const int* __restrict__ src, const int* __restrict__ dst) {
    int i = blockIdx.x*blockDim.x + threadIdx.x;
    int stride = gridDim.x*blockDim.x;
    for (int e = i; e < NE; e += stride) {
        int d = dst[e];
        int p = atomicAdd(&d_cursor[d], 1);
        d_csr[p] = src[e];
    }
}

// ---------------- aggregation: one warp per dst node; fp16 gather -----------
// reads h16 (256B/row), accumulates fp32, writes fp32 sum + gcn
__global__ void k_aggregate(const __half* __restrict__ h16) {
    int gw   = (blockIdx.x*blockDim.x + threadIdx.x) >> 5;
    int lane = threadIdx.x & 31;
    if (gw >= NN) return;
    int beg = d_rowptr[gw], end = d_rowptr[gw+1];
    const uint2* h2 = reinterpret_cast<const uint2*>(h16);
    float4 s = {0.f,0.f,0.f,0.f};
    float4 g = {0.f,0.f,0.f,0.f};
    for (int e = beg; e < end; e++) {
        int src  = d_csr[e];
        float is = d_invsqrt[src];
        uint2 raw = h2[src*32 + lane];
        float2 lo = __half22float2(*reinterpret_cast<const __half2*>(&raw.x));
        float2 hi = __half22float2(*reinterpret_cast<const __half2*>(&raw.y));
        s.x += lo.x;    s.y += lo.y;    s.z += hi.x;    s.w += hi.y;
        g.x += lo.x*is; g.y += lo.y*is; g.z += hi.x*is; g.w += hi.y*is;
    }
    float isd = d_invsqrt[gw];
    int o = gw*32 + lane;
    reinterpret_cast<float4*>(d_sum)[o] = s;
    float4 gc = {g.x*isd, g.y*isd, g.z*isd, g.w*isd};
    reinterpret_cast<float4*>(d_gcn)[o] = gc;
}

// ---------------- pipelined TF32 tensor-core GEMM ----------------------------
// out[M,128] = sum_s A_s @ W_s  (+bias) (relu); also writes fp16 copy to out16
__global__ void __launch_bounds__(256)
k_gemm_pipe(const float* __restrict__ A0, const float* __restrict__ A1,
            const float* __restrict__ A2, const float* __restrict__ A3,
            const float* __restrict__ rs1,      // row scale for source 1 (or null)
            const uint32_t* __restrict__ Wt,    // [nsrc][128][128] tf32 n-major
            const float* __restrict__ bias,
            float* __restrict__ out, __half* __restrict__ out16,
            int M, int nsrc, int relu)
{
    extern __shared__ char smem[];
    float*    AsF = (float*)smem;                          // [2][STAGE_ELEMS]
    uint32_t* BsU = (uint32_t*)(smem + 2*STAGE_ELEMS*4);   // [2][STAGE_ELEMS]
    uint32_t asAddr = (uint32_t)__cvta_generic_to_shared(AsF);
    uint32_t bsAddr = (uint32_t)__cvta_generic_to_shared(BsU);

    const float* srcs[4] = {A0, A1, A2, A3};
    int tid  = threadIdx.x;
    int lane = tid & 31;
    int wid  = tid >> 5;
    int wm = (wid & 3) * 32;
    int wn = (wid >> 2) * 64;
    int lr = lane >> 2, lc = lane & 3;
    int row0 = blockIdx.x * 128;

    float inv_a[2][2];
    #pragma unroll
    for (int mt = 0; mt < 2; mt++) {
        int r0 = row0 + wm + mt*16 + lr;
        int r1 = r0 + 8;
        inv_a[mt][0] = (rs1 && r0 < M) ? rs1[r0] : 1.f;
        inv_a[mt][1] = (rs1 && r1 < M) ? rs1[r1] : 1.f;
    }

    float acc[2][8][4];
    #pragma unroll
    for (int mt = 0; mt < 2; mt++)
        #pragma unroll
        for (int nt = 0; nt < 8; nt++)
            #pragma unroll
            for (int c = 0; c < 4; c++) acc[mt][nt][c] = 0.f;

    const int C = nsrc * 4;

    auto issue = [&](int c) {
        int st = c & 1;
        int s  = c >> 2;
        int k0 = (c & 3) * 32;
        const float*    A  = srcs[s];
        const uint32_t* Wb = Wt + s*HH;
        #pragma unroll
        for (int i = 0; i < 4; i++) {
            int idx = tid + i*256;
            int m = idx >> 3, kg = (idx & 7) * 4;
            int r = row0 + m;
            const float* src = A + (size_t)(r < M ? r : 0)*H + k0 + kg;
            cp16(asAddr + (st*STAGE_ELEMS + m*SM_STRIDE + kg)*4, src, (r < M) ? 16 : 0);
        }
        #pragma unroll
        for (int i = 0; i < 4; i++) {
            int idx = tid + i*256;
            int n = idx >> 3, kg = (idx & 7) * 4;
            cp16(bsAddr + (st*STAGE_ELEMS + n*SM_STRIDE + kg)*4, Wb + n*H + k0 + kg, 16);
        }
        cp_commit();
    };

    issue(0);
    for (int c = 0; c < C; c++) {
        if (c + 1 < C) { issue(c + 1); cp_wait<1>(); }
        else           { cp_wait<0>(); }
        __syncthreads();

        int st = c & 1;
        int s  = c >> 2;
        bool dosc = (s == 1) && (rs1 != nullptr);
        const float*    Ab = AsF + st*STAGE_ELEMS;
        const uint32_t* Bb = BsU + st*STAGE_ELEMS;

        #pragma unroll
        for (int k8 = 0; k8 < 32; k8 += 8) {
            uint32_t bf[8][2];
            #pragma unroll
            for (int nt = 0; nt < 8; nt++) {
                int nrow = wn + nt*8 + lr;
                bf[nt][0] = Bb[nrow*SM_STRIDE + k8 + lc];
                bf[nt][1] = Bb[nrow*SM_STRIDE + k8 + 4 + lc];
            }
            #pragma unroll
            for (int mt = 0; mt < 2; mt++) {
                int m0 = wm + mt*16 + lr;
                float f0 = Ab[m0*SM_STRIDE + k8 + lc];
                float f1 = Ab[(m0+8)*SM_STRIDE + k8 + lc];
                float f2 = Ab[m0*SM_STRIDE + k8 + 4 + lc];
                float f3 = Ab[(m0+8)*SM_STRIDE + k8 + 4 + lc];
                if (dosc) {
                    f0 *= inv_a[mt][0]; f2 *= inv_a[mt][0];
                    f1 *= inv_a[mt][1]; f3 *= inv_a[mt][1];
                }
                uint32_t a0 = f2tf32(f0), a1 = f2tf32(f1);
                uint32_t a2 = f2tf32(f2), a3 = f2tf32(f3);
                #pragma unroll
                for (int nt = 0; nt < 8; nt++)
                    mma_tf32(acc[mt][nt], a0, a1, a2, a3, bf[nt][0], bf[nt][1]);
            }
        }
        __syncthreads();
    }

    // epilogue: fp32 out + fp16 copy
    #pragma unroll
    for (int mt = 0; mt < 2; mt++) {
        int r0 = row0 + wm + mt*16 + lr;
        int r1 = r0 + 8;
        #pragma unroll
        for (int nt = 0; nt < 8; nt++) {
            int c = wn + nt*8 + 2*lc;
            float b0 = bias ? bias[c]   : 0.f;
            float b1 = bias ? bias[c+1] : 0.f;
            float v0 = acc[mt][nt][0] + b0;
            float v1 = acc[mt][nt][1] + b1;
            float v2 = acc[mt][nt][2] + b0;
            float v3 = acc[mt][nt][3] + b1;
            if (relu) {
                v0 = fmaxf(v0, 0.f); v1 = fmaxf(v1, 0.f);
                v2 = fmaxf(v2, 0.f); v3 = fmaxf(v3, 0.f);
            }
            if (r0 < M) {
                out[r0*H + c] = v0; out[r0*H + c + 1] = v1;
                *reinterpret_cast<__half2*>(out16 + r0*H + c) = __floats2half2_rn(v0, v1);
            }
            if (r1 < M) {
                out[r1*H + c] = v2; out[r1*H + c + 1] = v3;
                *reinterpret_cast<__half2*>(out16 + r1*H + c) = __floats2half2_rn(v2, v3);
            }
        }
    }
}

// ---------------- readout: one block per graph, one thread per column -------
__global__ void k_readout(const float* __restrict__ h, int layer) {
    int gr = blockIdx.x;
    int c  = threadIdx.x;
    int beg = d_gstart[gr], end = d_gstart[gr+1];
    float s = 0.f, mx = -3.4e38f;
    for (int n = beg; n < end; n++) {
        float v = h[n*H + c];
        s += v;
        mx = fmaxf(mx, v);
    }
    int cnt = end - beg;
    float mean = s / (float)(cnt > 1 ? cnt : 1);
    if (cnt == 0) mx = 0.f;
    const float* w = d_ro + layer*3;
    d_gfeat[gr*((LAY+1)*H) + layer*H + c] = w[0]*mean + w[1]*mx + w[2]*s;
}

// ---------------- head: relu(g @ Wl + bl) @ Wc + bc -------------------------
__global__ void k_head(const float* __restrict__ Wl, const float* __restrict__ bl,
                       const float* __restrict__ Wc, const float* __restrict__ bc,
                       float* __restrict__ out) {
    __shared__ float sg[(LAY+1)*H];
    __shared__ float mid[H];
    int gr = blockIdx.x;
    int t  = threadIdx.x;
    for (int i = t; i < (LAY+1)*H; i += H) sg[i] = d_gfeat[gr*((LAY+1)*H) + i];
    __syncthreads();
    float acc = bl[t];
    for (int k = 0; k < (LAY+1)*H; k++) acc += sg[k]*Wl[k*H + t];
    mid[t] = fmaxf(acc, 0.f);
    __syncthreads();
    if (t < NOUT) {
        float a = bc[t];
        for (int k = 0; k < H; k++) a += mid[k]*Wc[k*NOUT + t];
        out[gr*NOUT + t] = a;
    }
}

// ---------------- launch ----------------------------------------------------
extern "C" void kernel_launch(void* const* d_in, const int* in_sizes, int n_in,
                              void* d_out, int out_size) {
    const float* x      = (const float*)d_in[0];
    const int*   ei     = (const int*)  d_in[1];
    const int*   batch  = (const int*)  d_in[2];
    const float* lin1_W = (const float*)d_in[3];
    const float* lin1_b = (const float*)d_in[4];
    const float* Wna    = (const float*)d_in[5];
    const float* lna    = (const float*)d_in[6];
    const float* lro    = (const float*)d_in[7];
    const float* lout_W = (const float*)d_in[8];
    const float* lout_b = (const float*)d_in[9];
    const float* cls_W  = (const float*)d_in[10];
    const float* cls_b  = (const float*)d_in[11];
    const int* srcp = ei;
    const int* dstp = ei + NE;

    float *hA, *hB, *psum, *pgcn, *pinvdeg;
    __half *h16A, *h16B;
    uint32_t* pWt;
    int *pdeg, *prowptr, *pbhist, *pgstart;
    cudaGetSymbolAddress((void**)&hA,      d_hA);
    cudaGetSymbolAddress((void**)&hB,      d_hB);
    cudaGetSymbolAddress((void**)&h16A,    d_h16A);
    cudaGetSymbolAddress((void**)&h16B,    d_h16B);
    cudaGetSymbolAddress((void**)&psum,    d_sum);
    cudaGetSymbolAddress((void**)&pgcn,    d_gcn);
    cudaGetSymbolAddress((void**)&pWt,     d_Wt);
    cudaGetSymbolAddress((void**)&pinvdeg, d_invdeg);
    cudaGetSymbolAddress((void**)&pdeg,    d_deg);
    cudaGetSymbolAddress((void**)&prowptr, d_rowptr);
    cudaGetSymbolAddress((void**)&pbhist,  d_bhist);
    cudaGetSymbolAddress((void**)&pgstart, d_gstart);

    cudaFuncSetAttribute(k_gemm_pipe,
                         cudaFuncAttributeMaxDynamicSharedMemorySize, GEMM_SMEM);

    k_init<<<(NN+255)/256, 256>>>(lna, lro);
    k_wcomb<<<(NWMAT*HH+255)/256, 256>>>(Wna, lin1_W);
    k_hist<<<1024, 256>>>(dstp, batch);
    k_scan1<<<NB_SCAN, 1024>>>(pdeg, prowptr, NN);
    k_scan2<<<1, 32>>>(prowptr, NN, NB_SCAN);
    k_scan3c<<<NB_SCAN, 1024>>>(prowptr, NN);
    k_scan_small<<<1, 1024>>>(pbhist, pgstart, NG);
    k_scatter<<<1024, 256>>>(srcp, dstp);

    int gblocks = (NN + 127) / 128;
    // h = x @ lin1_W + b   (lin1 weights live in slot LAY*4 of d_Wt)
    k_gemm_pipe<<<gblocks, 256, GEMM_SMEM>>>(x, x, x, x, nullptr,
                                             pWt + (LAY*4)*HH, lin1_b,
                                             hA, h16A, NN, 1, 0);
    k_readout<<<NG, H>>>(hA, 0);

    float* cur = hA;  __half* cur16 = h16A;
    float* nxt = hB;  __half* nxt16 = h16B;
    for (int l = 0; l < LAY; l++) {
        k_aggregate<<<(NN*32+255)/256, 256>>>(cur16);
        // sources: h, sum*invdeg (mean), sum, gcn
        k_gemm_pipe<<<gblocks, 256, GEMM_SMEM>>>(cur, psum, psum, pgcn, pinvdeg,
                                                 pWt + l*4*HH, nullptr,
                                                 nxt, nxt16, NN, 4, 1);
        k_readout<<<NG, H>>>(nxt, l+1);
        float* t = cur; cur = nxt; nxt = t;
        __half* t16 = cur16; cur16 = nxt16; nxt16 = t16;
    }
    k_head<<<NG, H>>>(lout_W, lout_b, cls_W, cls_b, (float*)d_out);
}

// round 7
// speedup vs baseline: 4.4630x; 1.2516x over previous
#include <cuda_runtime.h>
#include <cuda_fp16.h>
#include <math.h>
#include <stdint.h>

#define NN 50000
#define NE 800000
#define H 128
#define LAY 3
#define NG 512
#define NOUT 10
#define HH (H*H)
#define NB_SCAN ((NN + 1023) / 1024)
#define NWMAT (LAY*4 + 1)          // 12 combined + 1 lin1
#define STRIDE_H 40                // halves; 80B rows, conflict-free
#define STAGE_H (128*STRIDE_H)
#define GEMM_SMEM (4*STAGE_H*2)    // As[2]+Bs[2] halves = 40960 B

// ---------------- scratch (static device globals) ---------------------------
__device__ __half   d_x16[NN*H];
__device__ __half   d_h16A[NN*H];
__device__ __half   d_h16B[NN*H];
__device__ __half   d_s16[NN*H];     // sum
__device__ __half   d_m16[NN*H];     // mean
__device__ __half   d_g16[NN*H];     // gcn
__device__ __half   d_Wh[NWMAT*HH];  // fp16 weights, [mat][n][k]
__device__ float    d_na[LAY*4];
__device__ float    d_ro[(LAY+1)*3];
__device__ int      d_deg[NN];
__device__ int      d_rowptr[NN+1];
__device__ int      d_cursor[NN];
__device__ int      d_csr[NE];
__device__ float    d_invdeg[NN];
__device__ float    d_invsqrt[NN];
__device__ int      d_bhist[NG];
__device__ int      d_gstart[NG+1];
__device__ float    d_gfeat[NG*(LAY+1)*H];
__device__ int      d_btot[NB_SCAN];
__device__ int      d_boff[NB_SCAN];

// ---------------- helpers ----------------------------------------------------
__device__ __forceinline__ void cp16(uint32_t dst, const void* src, int sz) {
    asm volatile("cp.async.ca.shared.global [%0], [%1], 16, %2;"
                 :: "r"(dst), "l"(src), "r"(sz));
}
__device__ __forceinline__ void cp_commit() {
    asm volatile("cp.async.commit_group;");
}
template<int N>
__device__ __forceinline__ void cp_wait() {
    asm volatile("cp.async.wait_group %0;" :: "n"(N));
}

__device__ __forceinline__ void mma_f16(float* acc,
                                        uint32_t a0, uint32_t a1, uint32_t a2, uint32_t a3,
                                        uint32_t b0, uint32_t b1) {
    asm volatile(
        "mma.sync.aligned.m16n8k16.row.col.f32.f16.f16.f32 "
        "{%0,%1,%2,%3}, {%4,%5,%6,%7}, {%8,%9}, {%0,%1,%2,%3};"
        : "+f"(acc[0]), "+f"(acc[1]), "+f"(acc[2]), "+f"(acc[3])
        : "r"(a0), "r"(a1), "r"(a2), "r"(a3), "r"(b0), "r"(b1));
}

// ---------------- init: zero counters + alpha softmaxes ----------------------
__global__ void k_init(const float* __restrict__ lna, const float* __restrict__ lro) {
    int i = blockIdx.x*blockDim.x + threadIdx.x;
    if (i < NN) d_deg[i] = 0;
    if (i < NG) d_bhist[i] = 0;
    if (i == 0) {
        for (int l = 0; l < LAY; l++) {
            float m = -1e30f;
            for (int j = 0; j < 4; j++) m = fmaxf(m, lna[l*4+j]);
            float e[4]; float s = 0.f;
            for (int j = 0; j < 4; j++) { e[j] = expf(lna[l*4+j]-m); s += e[j]; }
            for (int j = 0; j < 4; j++) d_na[l*4+j] = e[j]/s;
        }
        for (int l = 0; l < LAY+1; l++) {
            float m = -1e30f;
            for (int j = 0; j < 3; j++) m = fmaxf(m, lro[l*3+j]);
            float e[3]; float s = 0.f;
            for (int j = 0; j < 3; j++) { e[j] = expf(lro[l*3+j]-m); s += e[j]; }
            for (int j = 0; j < 3; j++) d_ro[l*3+j] = e[j]/s;
        }
    }
}

// x -> fp16
__global__ void k_tohalf(const float* __restrict__ x) {
    int i = blockIdx.x*blockDim.x + threadIdx.x;
    if (i < NN*H/2) {
        float2 v = reinterpret_cast<const float2*>(x)[i];
        reinterpret_cast<__half2*>(d_x16)[i] = __floats2half2_rn(v.x, v.y);
    }
}

// Combined per-layer weights, fp16, transposed to [mat][n][k]:
//   s0 (h)    : w1*W1 + w2*W3 + w3*W4
//   s1 (mean) : w1*W2
//   s2 (sum)  : w2*W3
//   s3 (gcn)  : w0*W0
//   mat 12    : lin1_W
__global__ void k_wcomb(const float* __restrict__ Wna, const float* __restrict__ lin1_W) {
    int i = blockIdx.x*blockDim.x + threadIdx.x;
    if (i >= NWMAT*HH) return;
    int mat = i/HH; int e = i%HH;
    int k = e >> 7, n = e & 127;
    float v;
    if (mat < LAY*4) {
        int l = mat >> 2, s = mat & 3;
        const float* W  = Wna + l*5*HH;
        const float* na = d_na + l*4;
        int idx = k*H + n;
        if (s == 0)      v = na[1]*W[1*HH+idx] + na[2]*W[3*HH+idx] + na[3]*W[4*HH+idx];
        else if (s == 1) v = na[1]*W[2*HH+idx];
        else if (s == 2) v = na[2]*W[3*HH+idx];
        else             v = na[0]*W[0*HH+idx];
    } else {
        v = lin1_W[k*H + n];
    }
    d_Wh[mat*HH + n*H + k] = __float2half(v);
}

__global__ void k_hist(const int* __restrict__ dst, const int* __restrict__ batch) {
    int i = blockIdx.x*blockDim.x + threadIdx.x;
    int stride = gridDim.x*blockDim.x;
    for (int e = i; e < NE; e += stride) atomicAdd(&d_deg[dst[e]], 1);
    for (int n = i; n < NN; n += stride) atomicAdd(&d_bhist[batch[n]], 1);
}

// ---- hierarchical scan for NN ----
__global__ void k_scan1(const int* __restrict__ in, int* __restrict__ out, int n) {
    __shared__ int wsum[32];
    int i = blockIdx.x*1024 + threadIdx.x;
    int lane = threadIdx.x & 31, warp = threadIdx.x >> 5;
    int v = (i < n) ? in[i] : 0;
    int x = v;
    #pragma unroll
    for (int o = 1; o < 32; o <<= 1) {
        int y = __shfl_up_sync(0xffffffffu, x, o);
        if (lane >= o) x += y;
    }
    if (lane == 31) wsum[warp] = x;
    __syncthreads();
    if (warp == 0) {
        int s = wsum[lane];
        #pragma unroll
        for (int o = 1; o < 32; o <<= 1) {
            int y = __shfl_up_sync(0xffffffffu, s, o);
            if (lane >= o) s += y;
        }
        wsum[lane] = s;
    }
    __syncthreads();
    int incl = x + (warp ? wsum[warp-1] : 0);
    if (i < n) out[i] = incl - v;
    if (threadIdx.x == 1023) d_btot[blockIdx.x] = incl;
}

__global__ void k_scan2(int* __restrict__ out, int n, int nb) {
    if (threadIdx.x == 0) {
        int acc = 0;
        for (int b = 0; b < nb; b++) { d_boff[b] = acc; acc += d_btot[b]; }
        out[n] = acc;
    }
}

// add block offsets; also init cursor + degree stats (fused)
__global__ void k_scan3c(int* __restrict__ out, int n) {
    int i = blockIdx.x*blockDim.x + threadIdx.x;
    if (i >= n) return;
    int v = out[i] + d_boff[i >> 10];
    out[i] = v;
    d_cursor[i] = v;
    int c = d_deg[i];
    float m = (float)(c > 1 ? c : 1);
    d_invdeg[i]  = 1.0f/m;
    d_invsqrt[i] = rsqrtf(m);
}

// single-block scan (for NG=512, blockDim=1024)
__global__ void k_scan_small(const int* __restrict__ in, int* __restrict__ out, int n) {
    __shared__ int wsum[32];
    int lane = threadIdx.x & 31, warp = threadIdx.x >> 5;
    int i = threadIdx.x;
    int v = (i < n) ? in[i] : 0;
    int x = v;
    #pragma unroll
    for (int o = 1; o < 32; o <<= 1) {
        int y = __shfl_up_sync(0xffffffffu, x, o);
        if (lane >= o) x += y;
    }
    if (lane == 31) wsum[warp] = x;
    __syncthreads();
    if (warp == 0) {
        int s = wsum[lane];
        #pragma unroll
        for (int o = 1; o < 32; o <<= 1) {
            int y = __shfl_up_sync(0xffffffffu, s, o);
            if (lane >= o) s += y;
        }
        wsum[lane] = s;
    }
    __syncthreads();
    int incl = x + (warp ? wsum[warp-1] : 0);
    if (i < n) out[i] = incl - v;
    if (i == n-1) out[n] = incl;
}

__global__ void k_scatter(const int* __restrict__ src, const int* __restrict__ dst) {
    int i = blockIdx.x*blockDim.x + threadIdx.x;
    int stride = gridDim.x*blockDim.x;
    for (int e = i; e < NE; e += stride) {
        int d = dst[e];
        int p = atomicAdd(&d_cursor[d], 1);
        d_csr[p] = src[e];
    }
}

// ---------------- aggregation: one warp per dst node; all fp16 --------------
// reads h16, accumulates fp32, writes fp16 sum / mean / gcn
__global__ void k_aggregate(const __half* __restrict__ h16) {
    int gw   = (blockIdx.x*blockDim.x + threadIdx.x) >> 5;
    int lane = threadIdx.x & 31;
    if (gw >= NN) return;
    int beg = d_rowptr[gw], end = d_rowptr[gw+1];
    const uint2* h2 = reinterpret_cast<const uint2*>(h16);
    float4 s = {0.f,0.f,0.f,0.f};
    float4 g = {0.f,0.f,0.f,0.f};
    for (int e = beg; e < end; e++) {
        int src  = d_csr[e];
        float is = d_invsqrt[src];
        uint2 raw = h2[src*32 + lane];
        float2 lo = __half22float2(*reinterpret_cast<const __half2*>(&raw.x));
        float2 hi = __half22float2(*reinterpret_cast<const __half2*>(&raw.y));
        s.x += lo.x;    s.y += lo.y;    s.z += hi.x;    s.w += hi.y;
        g.x += lo.x*is; g.y += lo.y*is; g.z += hi.x*is; g.w += hi.y*is;
    }
    float id  = d_invdeg[gw];
    float isd = d_invsqrt[gw];
    int o = gw*32 + lane;
    uint2 su, mu, gu;
    *reinterpret_cast<__half2*>(&su.x) = __floats2half2_rn(s.x, s.y);
    *reinterpret_cast<__half2*>(&su.y) = __floats2half2_rn(s.z, s.w);
    *reinterpret_cast<__half2*>(&mu.x) = __floats2half2_rn(s.x*id, s.y*id);
    *reinterpret_cast<__half2*>(&mu.y) = __floats2half2_rn(s.z*id, s.w*id);
    *reinterpret_cast<__half2*>(&gu.x) = __floats2half2_rn(g.x*isd, g.y*isd);
    *reinterpret_cast<__half2*>(&gu.y) = __floats2half2_rn(g.z*isd, g.w*isd);
    reinterpret_cast<uint2*>(d_s16)[o] = su;
    reinterpret_cast<uint2*>(d_m16)[o] = mu;
    reinterpret_cast<uint2*>(d_g16)[o] = gu;
}

// ---------------- pipelined FP16 tensor-core GEMM ----------------------------
// out16[M,128] = sum_s A_s @ W_s  (+bias) (relu); all operands fp16, fp32 accum
// BM=128, BN=128, K chunks of 32 over flattened (source, kt); 2-stage cp.async
__global__ void __launch_bounds__(256)
k_gemm_f16(const __half* __restrict__ A0, const __half* __restrict__ A1,
           const __half* __restrict__ A2, const __half* __restrict__ A3,
           const __half* __restrict__ Wh,     // [nsrc][128][128] fp16 n-major
           const float* __restrict__ bias,
           __half* __restrict__ out16, int M, int nsrc, int relu)
{
    extern __shared__ char smem[];
    __half* AsH = (__half*)smem;                     // [2][STAGE_H]
    __half* BsH = (__half*)smem + 2*STAGE_H;         // [2][STAGE_H]
    uint32_t asAddr = (uint32_t)__cvta_generic_to_shared(AsH);
    uint32_t bsAddr = (uint32_t)__cvta_generic_to_shared(BsH);

    const __half* srcs[4] = {A0, A1, A2, A3};
    int tid  = threadIdx.x;
    int lane = tid & 31;
    int wid  = tid >> 5;
    int wm = (wid & 3) * 32;
    int wn = (wid >> 2) * 64;
    int lr = lane >> 2, lc = lane & 3;
    int row0 = blockIdx.x * 128;

    float acc[2][8][4];
    #pragma unroll
    for (int mt = 0; mt < 2; mt++)
        #pragma unroll
        for (int nt = 0; nt < 8; nt++)
            #pragma unroll
            for (int c = 0; c < 4; c++) acc[mt][nt][c] = 0.f;

    const int C = nsrc * 4;

    auto issue = [&](int c) {
        int st = c & 1;
        int s  = c >> 2;
        int k0 = (c & 3) * 32;
        const __half* A  = srcs[s];
        const __half* Wb = Wh + s*HH;
        // A tile: 128 rows x 32 halves = 64B/row -> 4 cp16/row, 2 per thread
        #pragma unroll
        for (int i = 0; i < 2; i++) {
            int idx = tid + i*256;
            int m = idx >> 2, kg = (idx & 3) * 8;
            int r = row0 + m;
            const __half* src = A + (size_t)(r < M ? r : 0)*H + k0 + kg;
            cp16(asAddr + (st*STAGE_H + m*STRIDE_H + kg)*2, src, (r < M) ? 16 : 0);
        }
        #pragma unroll
        for (int i = 0; i < 2; i++) {
            int idx = tid + i*256;
            int n = idx >> 2, kg = (idx & 3) * 8;
            cp16(bsAddr + (st*STAGE_H + n*STRIDE_H + kg)*2, Wb + n*H + k0 + kg, 16);
        }
        cp_commit();
    };

    issue(0);
    for (int c = 0; c < C; c++) {
        if (c + 1 < C) { issue(c + 1); cp_wait<1>(); }
        else           { cp_wait<0>(); }
        __syncthreads();

        int st = c & 1;
        const __half* Ab = AsH + st*STAGE_H;
        const __half* Bb = BsH + st*STAGE_H;

        #pragma unroll
        for (int kb = 0; kb < 32; kb += 16) {
            uint32_t bf[8][2];
            #pragma unroll
            for (int nt = 0; nt < 8; nt++) {
                int nrow = wn + nt*8 + lr;
                bf[nt][0] = *reinterpret_cast<const uint32_t*>(&Bb[nrow*STRIDE_H + kb + 2*lc]);
                bf[nt][1] = *reinterpret_cast<const uint32_t*>(&Bb[nrow*STRIDE_H + kb + 8 + 2*lc]);
            }
            #pragma unroll
            for (int mt = 0; mt < 2; mt++) {
                int m0 = wm + mt*16 + lr;
                uint32_t a0 = *reinterpret_cast<const uint32_t*>(&Ab[m0*STRIDE_H + kb + 2*lc]);
                uint32_t a1 = *reinterpret_cast<const uint32_t*>(&Ab[(m0+8)*STRIDE_H + kb + 2*lc]);
                uint32_t a2 = *reinterpret_cast<const uint32_t*>(&Ab[m0*STRIDE_H + kb + 8 + 2*lc]);
                uint32_t a3 = *reinterpret_cast<const uint32_t*>(&Ab[(m0+8)*STRIDE_H + kb + 8 + 2*lc]);
                #pragma unroll
                for (int nt = 0; nt < 8; nt++)
                    mma_f16(acc[mt][nt], a0, a1, a2, a3, bf[nt][0], bf[nt][1]);
            }
        }
        __syncthreads();
    }

    // epilogue: fp16 out
    #pragma unroll
    for (int mt = 0; mt < 2; mt++) {
        int r0 = row0 + wm + mt*16 + lr;
        int r1 = r0 + 8;
        #pragma unroll
        for (int nt = 0; nt < 8; nt++) {
            int c = wn + nt*8 + 2*lc;
            float b0 = bias ? bias[c]   : 0.f;
            float b1 = bias ? bias[c+1] : 0.f;
            float v0 = acc[mt][nt][0] + b0;
            float v1 = acc[mt][nt][1] + b1;
            float v2 = acc[mt][nt][2] + b0;
            float v3 = acc[mt][nt][3] + b1;
            if (relu) {
                v0 = fmaxf(v0, 0.f); v1 = fmaxf(v1, 0.f);
                v2 = fmaxf(v2, 0.f); v3 = fmaxf(v3, 0.f);
            }
            if (r0 < M)
                *reinterpret_cast<__half2*>(out16 + r0*H + c) = __floats2half2_rn(v0, v1);
            if (r1 < M)
                *reinterpret_cast<__half2*>(out16 + r1*H + c) = __floats2half2_rn(v2, v3);
        }
    }
}

// ---------------- readout: one block per graph, one thread per column -------
__global__ void k_readout(const __half* __restrict__ h16, int layer) {
    int gr = blockIdx.x;
    int c  = threadIdx.x;
    int beg = d_gstart[gr], end = d_gstart[gr+1];
    float s = 0.f, mx = -3.4e38f;
    for (int n = beg; n < end; n++) {
        float v = __half2float(h16[n*H + c]);
        s += v;
        mx = fmaxf(mx, v);
    }
    int cnt = end - beg;
    float mean = s / (float)(cnt > 1 ? cnt : 1);
    if (cnt == 0) mx = 0.f;
    const float* w = d_ro + layer*3;
    d_gfeat[gr*((LAY+1)*H) + layer*H + c] = w[0]*mean + w[1]*mx + w[2]*s;
}

// ---------------- head: relu(g @ Wl + bl) @ Wc + bc -------------------------
__global__ void k_head(const float* __restrict__ Wl, const float* __restrict__ bl,
                       const float* __restrict__ Wc, const float* __restrict__ bc,
                       float* __restrict__ out) {
    __shared__ float sg[(LAY+1)*H];
    __shared__ float mid[H];
    int gr = blockIdx.x;
    int t  = threadIdx.x;
    for (int i = t; i < (LAY+1)*H; i += H) sg[i] = d_gfeat[gr*((LAY+1)*H) + i];
    __syncthreads();
    float acc = bl[t];
    for (int k = 0; k < (LAY+1)*H; k++) acc += sg[k]*Wl[k*H + t];
    mid[t] = fmaxf(acc, 0.f);
    __syncthreads();
    if (t < NOUT) {
        float a = bc[t];
        for (int k = 0; k < H; k++) a += mid[k]*Wc[k*NOUT + t];
        out[gr*NOUT + t] = a;
    }
}

// ---------------- launch ----------------------------------------------------
extern "C" void kernel_launch(void* const* d_in, const int* in_sizes, int n_in,
                              void* d_out, int out_size) {
    const float* x      = (const float*)d_in[0];
    const int*   ei     = (const int*)  d_in[1];
    const int*   batch  = (const int*)  d_in[2];
    const float* lin1_W = (const float*)d_in[3];
    const float* lin1_b = (const float*)d_in[4];
    const float* Wna    = (const float*)d_in[5];
    const float* lna    = (const float*)d_in[6];
    const float* lro    = (const float*)d_in[7];
    const float* lout_W = (const float*)d_in[8];
    const float* lout_b = (const float*)d_in[9];
    const float* cls_W  = (const float*)d_in[10];
    const float* cls_b  = (const float*)d_in[11];
    const int* srcp = ei;
    const int* dstp = ei + NE;

    __half *x16, *h16A, *h16B, *s16, *m16, *g16, *pWh;
    int *pdeg, *prowptr, *pbhist, *pgstart;
    cudaGetSymbolAddress((void**)&x16,     d_x16);
    cudaGetSymbolAddress((void**)&h16A,    d_h16A);
    cudaGetSymbolAddress((void**)&h16B,    d_h16B);
    cudaGetSymbolAddress((void**)&s16,     d_s16);
    cudaGetSymbolAddress((void**)&m16,     d_m16);
    cudaGetSymbolAddress((void**)&g16,     d_g16);
    cudaGetSymbolAddress((void**)&pWh,     d_Wh);
    cudaGetSymbolAddress((void**)&pdeg,    d_deg);
    cudaGetSymbolAddress((void**)&prowptr, d_rowptr);
    cudaGetSymbolAddress((void**)&pbhist,  d_bhist);
    cudaGetSymbolAddress((void**)&pgstart, d_gstart);

    cudaFuncSetAttribute(k_gemm_f16,
                         cudaFuncAttributeMaxDynamicSharedMemorySize, GEMM_SMEM);

    int gblocks = (NN + 127) / 128;

    k_init<<<(NN+255)/256, 256>>>(lna, lro);
    k_tohalf<<<(NN*H/2+255)/256, 256>>>(x);
    k_wcomb<<<(NWMAT*HH+255)/256, 256>>>(Wna, lin1_W);
    // launch index 3 -> ncu capture lands here: lin1 GEMM
    k_gemm_f16<<<gblocks, 256, GEMM_SMEM>>>(x16, x16, x16, x16,
                                            pWh + (LAY*4)*HH, lin1_b,
                                            h16A, NN, 1, 0);
    k_hist<<<1024, 256>>>(dstp, batch);
    k_scan1<<<NB_SCAN, 1024>>>(pdeg, prowptr, NN);
    k_scan2<<<1, 32>>>(prowptr, NN, NB_SCAN);
    k_scan3c<<<NB_SCAN, 1024>>>(prowptr, NN);
    k_scan_small<<<1, 1024>>>(pbhist, pgstart, NG);
    k_scatter<<<1024, 256>>>(srcp, dstp);
    k_readout<<<NG, H>>>(h16A, 0);

    __half* cur16 = h16A;
    __half* nxt16 = h16B;
    for (int l = 0; l < LAY; l++) {
        k_aggregate<<<(NN*32+255)/256, 256>>>(cur16);
        // sources: h, mean, sum, gcn — all fp16
        k_gemm_f16<<<gblocks, 256, GEMM_SMEM>>>(cur16, m16, s16, g16,
                                                pWh + l*4*HH, nullptr,
                                                nxt16, NN, 4, 1);
        k_readout<<<NG, H>>>(nxt16, l+1);
        __half* t16 = cur16; cur16 = nxt16; nxt16 = t16;
    }
    k_head<<<NG, H>>>(lout_W, lout_b, cls_W, cls_b, (float*)d_out);
}

// round 8
// speedup vs baseline: 4.6211x; 1.0354x over previous
#include <cuda_runtime.h>
#include <cuda_fp16.h>
#include <math.h>
#include <stdint.h>

#define NN 50000
#define NE 800000
#define H 128
#define LAY 3
#define NG 512
#define NOUT 10
#define HH (H*H)
#define NB_SCAN ((NN + 1023) / 1024)
#define NWMAT (LAY*4 + 1)          // 12 combined + 1 lin1
#define STRIDE_H 40                // halves; 80B rows -> LDSM conflict-free
#define STAGE_H (128*STRIDE_H)
#define GEMM_SMEM (4*STAGE_H*2)    // As[2]+Bs[2] halves = 40960 B

// ---------------- scratch (static device globals) ---------------------------
__device__ __half   d_x16[NN*H];
__device__ __half   d_h16A[NN*H];
__device__ __half   d_h16B[NN*H];
__device__ __half   d_s16[NN*H];     // sum
__device__ __half   d_m16[NN*H];     // mean
__device__ __half   d_g16[NN*H];     // gcn
__device__ __half   d_Wh[NWMAT*HH];  // fp16 weights, [mat][n][k]
__device__ float    d_na[LAY*4];
__device__ float    d_ro[(LAY+1)*3];
__device__ int      d_deg[NN];
__device__ int      d_rowptr[NN+1];
__device__ int      d_cursor[NN];
__device__ int      d_csr[NE];
__device__ float    d_invdeg[NN];
__device__ float    d_invsqrt[NN];
__device__ int      d_bhist[NG];
__device__ int      d_gstart[NG+1];
__device__ float    d_gfeat[NG*(LAY+1)*H];
__device__ int      d_btot[NB_SCAN];
__device__ int      d_boff[NB_SCAN];

// ---------------- helpers ----------------------------------------------------
__device__ __forceinline__ void cp16(uint32_t dst, const void* src, int sz) {
    asm volatile("cp.async.ca.shared.global [%0], [%1], 16, %2;"
                 :: "r"(dst), "l"(src), "r"(sz));
}
__device__ __forceinline__ void cp_commit() {
    asm volatile("cp.async.commit_group;");
}
template<int N>
__device__ __forceinline__ void cp_wait() {
    asm volatile("cp.async.wait_group %0;" :: "n"(N));
}

__device__ __forceinline__ void ldsm4(uint32_t& r0, uint32_t& r1, uint32_t& r2, uint32_t& r3,
                                      uint32_t addr) {
    asm volatile("ldmatrix.sync.aligned.m8n8.x4.shared.b16 {%0,%1,%2,%3}, [%4];"
                 : "=r"(r0), "=r"(r1), "=r"(r2), "=r"(r3) : "r"(addr));
}

__device__ __forceinline__ void mma_f16(float* acc,
                                        uint32_t a0, uint32_t a1, uint32_t a2, uint32_t a3,
                                        uint32_t b0, uint32_t b1) {
    asm volatile(
        "mma.sync.aligned.m16n8k16.row.col.f32.f16.f16.f32 "
        "{%0,%1,%2,%3}, {%4,%5,%6,%7}, {%8,%9}, {%0,%1,%2,%3};"
        : "+f"(acc[0]), "+f"(acc[1]), "+f"(acc[2]), "+f"(acc[3])
        : "r"(a0), "r"(a1), "r"(a2), "r"(a3), "r"(b0), "r"(b1));
}

// ---------------- init: zero counters + alpha softmaxes ----------------------
__global__ void k_init(const float* __restrict__ lna, const float* __restrict__ lro) {
    int i = blockIdx.x*blockDim.x + threadIdx.x;
    if (i < NN) d_deg[i] = 0;
    if (i < NG) d_bhist[i] = 0;
    if (i == 0) {
        for (int l = 0; l < LAY; l++) {
            float m = -1e30f;
            for (int j = 0; j < 4; j++) m = fmaxf(m, lna[l*4+j]);
            float e[4]; float s = 0.f;
            for (int j = 0; j < 4; j++) { e[j] = expf(lna[l*4+j]-m); s += e[j]; }
            for (int j = 0; j < 4; j++) d_na[l*4+j] = e[j]/s;
        }
        for (int l = 0; l < LAY+1; l++) {
            float m = -1e30f;
            for (int j = 0; j < 3; j++) m = fmaxf(m, lro[l*3+j]);
            float e[3]; float s = 0.f;
            for (int j = 0; j < 3; j++) { e[j] = expf(lro[l*3+j]-m); s += e[j]; }
            for (int j = 0; j < 3; j++) d_ro[l*3+j] = e[j]/s;
        }
    }
}

// x -> fp16
__global__ void k_tohalf(const float* __restrict__ x) {
    int i = blockIdx.x*blockDim.x + threadIdx.x;
    if (i < NN*H/2) {
        float2 v = reinterpret_cast<const float2*>(x)[i];
        reinterpret_cast<__half2*>(d_x16)[i] = __floats2half2_rn(v.x, v.y);
    }
}

// Combined per-layer weights, fp16, transposed to [mat][n][k]
__global__ void k_wcomb(const float* __restrict__ Wna, const float* __restrict__ lin1_W) {
    int i = blockIdx.x*blockDim.x + threadIdx.x;
    if (i >= NWMAT*HH) return;
    int mat = i/HH; int e = i%HH;
    int k = e >> 7, n = e & 127;
    float v;
    if (mat < LAY*4) {
        int l = mat >> 2, s = mat & 3;
        const float* W  = Wna + l*5*HH;
        const float* na = d_na + l*4;
        int idx = k*H + n;
        if (s == 0)      v = na[1]*W[1*HH+idx] + na[2]*W[3*HH+idx] + na[3]*W[4*HH+idx];
        else if (s == 1) v = na[1]*W[2*HH+idx];
        else if (s == 2) v = na[2]*W[3*HH+idx];
        else             v = na[0]*W[0*HH+idx];
    } else {
        v = lin1_W[k*H + n];
    }
    d_Wh[mat*HH + n*H + k] = __float2half(v);
}

// vectorized histograms: edges via int4, nodes via int2
__global__ void k_hist(const int* __restrict__ dst, const int* __restrict__ batch) {
    int i = blockIdx.x*blockDim.x + threadIdx.x;
    int stride = gridDim.x*blockDim.x;
    const int4* d4 = reinterpret_cast<const int4*>(dst);
    for (int e = i; e < NE/4; e += stride) {
        int4 v = d4[e];
        atomicAdd(&d_deg[v.x], 1);
        atomicAdd(&d_deg[v.y], 1);
        atomicAdd(&d_deg[v.z], 1);
        atomicAdd(&d_deg[v.w], 1);
    }
    const int2* b2 = reinterpret_cast<const int2*>(batch);
    for (int n = i; n < NN/2; n += stride) {
        int2 v = b2[n];
        atomicAdd(&d_bhist[v.x], 1);
        atomicAdd(&d_bhist[v.y], 1);
    }
}

// ---- hierarchical scan for NN ----
__global__ void k_scan1(const int* __restrict__ in, int* __restrict__ out, int n) {
    __shared__ int wsum[32];
    int i = blockIdx.x*1024 + threadIdx.x;
    int lane = threadIdx.x & 31, warp = threadIdx.x >> 5;
    int v = (i < n) ? in[i] : 0;
    int x = v;
    #pragma unroll
    for (int o = 1; o < 32; o <<= 1) {
        int y = __shfl_up_sync(0xffffffffu, x, o);
        if (lane >= o) x += y;
    }
    if (lane == 31) wsum[warp] = x;
    __syncthreads();
    if (warp == 0) {
        int s = wsum[lane];
        #pragma unroll
        for (int o = 1; o < 32; o <<= 1) {
            int y = __shfl_up_sync(0xffffffffu, s, o);
            if (lane >= o) s += y;
        }
        wsum[lane] = s;
    }
    __syncthreads();
    int incl = x + (warp ? wsum[warp-1] : 0);
    if (i < n) out[i] = incl - v;
    if (threadIdx.x == 1023) d_btot[blockIdx.x] = incl;
}

__global__ void k_scan2(int* __restrict__ out, int n, int nb) {
    if (threadIdx.x == 0) {
        int acc = 0;
        for (int b = 0; b < nb; b++) { d_boff[b] = acc; acc += d_btot[b]; }
        out[n] = acc;
    }
}

__global__ void k_scan3c(int* __restrict__ out, int n) {
    int i = blockIdx.x*blockDim.x + threadIdx.x;
    if (i >= n) return;
    int v = out[i] + d_boff[i >> 10];
    out[i] = v;
    d_cursor[i] = v;
    int c = d_deg[i];
    float m = (float)(c > 1 ? c : 1);
    d_invdeg[i]  = 1.0f/m;
    d_invsqrt[i] = rsqrtf(m);
}

__global__ void k_scan_small(const int* __restrict__ in, int* __restrict__ out, int n) {
    __shared__ int wsum[32];
    int lane = threadIdx.x & 31, warp = threadIdx.x >> 5;
    int i = threadIdx.x;
    int v = (i < n) ? in[i] : 0;
    int x = v;
    #pragma unroll
    for (int o = 1; o < 32; o <<= 1) {
        int y = __shfl_up_sync(0xffffffffu, x, o);
        if (lane >= o) x += y;
    }
    if (lane == 31) wsum[warp] = x;
    __syncthreads();
    if (warp == 0) {
        int s = wsum[lane];
        #pragma unroll
        for (int o = 1; o < 32; o <<= 1) {
            int y = __shfl_up_sync(0xffffffffu, s, o);
            if (lane >= o) s += y;
        }
        wsum[lane] = s;
    }
    __syncthreads();
    int incl = x + (warp ? wsum[warp-1] : 0);
    if (i < n) out[i] = incl - v;
    if (i == n-1) out[n] = incl;
}

// vectorized scatter: int4 reads of src/dst
__global__ void k_scatter(const int* __restrict__ src, const int* __restrict__ dst) {
    int i = blockIdx.x*blockDim.x + threadIdx.x;
    int stride = gridDim.x*blockDim.x;
    const int4* s4 = reinterpret_cast<const int4*>(src);
    const int4* d4 = reinterpret_cast<const int4*>(dst);
    for (int e = i; e < NE/4; e += stride) {
        int4 sv = s4[e];
        int4 dv = d4[e];
        d_csr[atomicAdd(&d_cursor[dv.x], 1)] = sv.x;
        d_csr[atomicAdd(&d_cursor[dv.y], 1)] = sv.y;
        d_csr[atomicAdd(&d_cursor[dv.z], 1)] = sv.z;
        d_csr[atomicAdd(&d_cursor[dv.w], 1)] = sv.w;
    }
}

// ---------------- aggregation: one warp per dst node; all fp16 --------------
__global__ void k_aggregate(const __half* __restrict__ h16) {
    int gw   = (blockIdx.x*blockDim.x + threadIdx.x) >> 5;
    int lane = threadIdx.x & 31;
    if (gw >= NN) return;
    int beg = d_rowptr[gw], end = d_rowptr[gw+1];
    const uint2* h2 = reinterpret_cast<const uint2*>(h16);
    float4 s = {0.f,0.f,0.f,0.f};
    float4 g = {0.f,0.f,0.f,0.f};
    for (int e = beg; e < end; e++) {
        int src  = d_csr[e];
        float is = d_invsqrt[src];
        uint2 raw = h2[src*32 + lane];
        float2 lo = __half22float2(*reinterpret_cast<const __half2*>(&raw.x));
        float2 hi = __half22float2(*reinterpret_cast<const __half2*>(&raw.y));
        s.x += lo.x;    s.y += lo.y;    s.z += hi.x;    s.w += hi.y;
        g.x += lo.x*is; g.y += lo.y*is; g.z += hi.x*is; g.w += hi.y*is;
    }
    float id  = d_invdeg[gw];
    float isd = d_invsqrt[gw];
    int o = gw*32 + lane;
    uint2 su, mu, gu;
    *reinterpret_cast<__half2*>(&su.x) = __floats2half2_rn(s.x, s.y);
    *reinterpret_cast<__half2*>(&su.y) = __floats2half2_rn(s.z, s.w);
    *reinterpret_cast<__half2*>(&mu.x) = __floats2half2_rn(s.x*id, s.y*id);
    *reinterpret_cast<__half2*>(&mu.y) = __floats2half2_rn(s.z*id, s.w*id);
    *reinterpret_cast<__half2*>(&gu.x) = __floats2half2_rn(g.x*isd, g.y*isd);
    *reinterpret_cast<__half2*>(&gu.y) = __floats2half2_rn(g.z*isd, g.w*isd);
    reinterpret_cast<uint2*>(d_s16)[o] = su;
    reinterpret_cast<uint2*>(d_m16)[o] = mu;
    reinterpret_cast<uint2*>(d_g16)[o] = gu;
}

// ---------------- pipelined FP16 tensor-core GEMM + ldmatrix -----------------
// out16[M,128] = sum_s A_s @ W_s  (+bias) (relu)
__global__ void __launch_bounds__(256)
k_gemm_f16(const __half* __restrict__ A0, const __half* __restrict__ A1,
           const __half* __restrict__ A2, const __half* __restrict__ A3,
           const __half* __restrict__ Wh,     // [nsrc][128][128] fp16 n-major
           const float* __restrict__ bias,
           __half* __restrict__ out16, int M, int nsrc, int relu)
{
    extern __shared__ char smem[];
    __half* AsH = (__half*)smem;                     // [2][STAGE_H]
    __half* BsH = (__half*)smem + 2*STAGE_H;         // [2][STAGE_H]
    uint32_t asAddr = (uint32_t)__cvta_generic_to_shared(AsH);
    uint32_t bsAddr = (uint32_t)__cvta_generic_to_shared(BsH);

    const __half* srcs[4] = {A0, A1, A2, A3};
    int tid  = threadIdx.x;
    int lane = tid & 31;
    int wid  = tid >> 5;
    int wm = (wid & 3) * 32;
    int wn = (wid >> 2) * 64;
    int lr = lane >> 2, lc = lane & 3;
    int row0 = blockIdx.x * 128;

    // ldmatrix per-thread source offsets (bytes)
    // A x4 tiles (m0,k0),(m8,k0),(m0,k8),(m8,k8): lane->row m0+(lane&15), kcol 8*(lane>>4)
    uint32_t aoff = ((wm + (lane & 15)) * STRIDE_H + ((lane >> 4) << 3)) * 2;
    // B x4 tiles (n0,k0),(n0,k8),(n8,k0),(n8,k8): row n0+(lane&7)+((lane&16)>>1), kcol lane&8
    uint32_t boff = ((wn + (lane & 7) + ((lane & 16) >> 1)) * STRIDE_H + (lane & 8)) * 2;

    float acc[2][8][4];
    #pragma unroll
    for (int mt = 0; mt < 2; mt++)
        #pragma unroll
        for (int nt = 0; nt < 8; nt++)
            #pragma unroll
            for (int c = 0; c < 4; c++) acc[mt][nt][c] = 0.f;

    const int C = nsrc * 4;

    auto issue = [&](int c) {
        int st = c & 1;
        int s  = c >> 2;
        int k0 = (c & 3) * 32;
        const __half* A  = srcs[s];
        const __half* Wb = Wh + s*HH;
        #pragma unroll
        for (int i = 0; i < 2; i++) {
            int idx = tid + i*256;
            int m = idx >> 2, kg = (idx & 3) * 8;
            int r = row0 + m;
            const __half* src = A + (size_t)(r < M ? r : 0)*H + k0 + kg;
            cp16(asAddr + (st*STAGE_H + m*STRIDE_H + kg)*2, src, (r < M) ? 16 : 0);
        }
        #pragma unroll
        for (int i = 0; i < 2; i++) {
            int idx = tid + i*256;
            int n = idx >> 2, kg = (idx & 3) * 8;
            cp16(bsAddr + (st*STAGE_H + n*STRIDE_H + kg)*2, Wb + n*H + k0 + kg, 16);
        }
        cp_commit();
    };

    issue(0);
    for (int c = 0; c < C; c++) {
        if (c + 1 < C) { issue(c + 1); cp_wait<1>(); }
        else           { cp_wait<0>(); }
        __syncthreads();

        int st = c & 1;
        uint32_t aBase = asAddr + st*STAGE_H*2 + aoff;
        uint32_t bBase = bsAddr + st*STAGE_H*2 + boff;

        #pragma unroll
        for (int kb = 0; kb < 32; kb += 16) {
            uint32_t a[2][4];
            #pragma unroll
            for (int mt = 0; mt < 2; mt++)
                ldsm4(a[mt][0], a[mt][1], a[mt][2], a[mt][3],
                      aBase + (mt*16*STRIDE_H + kb)*2);
            uint32_t b[4][4];
            #pragma unroll
            for (int j = 0; j < 4; j++)
                ldsm4(b[j][0], b[j][1], b[j][2], b[j][3],
                      bBase + (j*16*STRIDE_H + kb)*2);
            #pragma unroll
            for (int mt = 0; mt < 2; mt++)
                #pragma unroll
                for (int j = 0; j < 4; j++) {
                    mma_f16(acc[mt][2*j],   a[mt][0], a[mt][1], a[mt][2], a[mt][3],
                            b[j][0], b[j][1]);
                    mma_f16(acc[mt][2*j+1], a[mt][0], a[mt][1], a[mt][2], a[mt][3],
                            b[j][2], b[j][3]);
                }
        }
        __syncthreads();
    }

    // epilogue: fp16 out
    #pragma unroll
    for (int mt = 0; mt < 2; mt++) {
        int r0 = row0 + wm + mt*16 + lr;
        int r1 = r0 + 8;
        #pragma unroll
        for (int nt = 0; nt < 8; nt++) {
            int c = wn + nt*8 + 2*lc;
            float b0 = bias ? bias[c]   : 0.f;
            float b1 = bias ? bias[c+1] : 0.f;
            float v0 = acc[mt][nt][0] + b0;
            float v1 = acc[mt][nt][1] + b1;
            float v2 = acc[mt][nt][2] + b0;
            float v3 = acc[mt][nt][3] + b1;
            if (relu) {
                v0 = fmaxf(v0, 0.f); v1 = fmaxf(v1, 0.f);
                v2 = fmaxf(v2, 0.f); v3 = fmaxf(v3, 0.f);
            }
            if (r0 < M)
                *reinterpret_cast<__half2*>(out16 + r0*H + c) = __floats2half2_rn(v0, v1);
            if (r1 < M)
                *reinterpret_cast<__half2*>(out16 + r1*H + c) = __floats2half2_rn(v2, v3);
        }
    }
}

// ---------------- readout: one block per graph, one thread per column -------
__global__ void k_readout(const __half* __restrict__ h16, int layer) {
    int gr = blockIdx.x;
    int c  = threadIdx.x;
    int beg = d_gstart[gr], end = d_gstart[gr+1];
    float s = 0.f, mx = -3.4e38f;
    for (int n = beg; n < end; n++) {
        float v = __half2float(h16[n*H + c]);
        s += v;
        mx = fmaxf(mx, v);
    }
    int cnt = end - beg;
    float mean = s / (float)(cnt > 1 ? cnt : 1);
    if (cnt == 0) mx = 0.f;
    const float* w = d_ro + layer*3;
    d_gfeat[gr*((LAY+1)*H) + layer*H + c] = w[0]*mean + w[1]*mx + w[2]*s;
}

// ---------------- head: relu(g @ Wl + bl) @ Wc + bc -------------------------
__global__ void k_head(const float* __restrict__ Wl, const float* __restrict__ bl,
                       const float* __restrict__ Wc, const float* __restrict__ bc,
                       float* __restrict__ out) {
    __shared__ float sg[(LAY+1)*H];
    __shared__ float mid[H];
    int gr = blockIdx.x;
    int t  = threadIdx.x;
    for (int i = t; i < (LAY+1)*H; i += H) sg[i] = d_gfeat[gr*((LAY+1)*H) + i];
    __syncthreads();
    float acc = bl[t];
    for (int k = 0; k < (LAY+1)*H; k++) acc += sg[k]*Wl[k*H + t];
    mid[t] = fmaxf(acc, 0.f);
    __syncthreads();
    if (t < NOUT) {
        float a = bc[t];
        for (int k = 0; k < H; k++) a += mid[k]*Wc[k*NOUT + t];
        out[gr*NOUT + t] = a;
    }
}

// ---------------- launch ----------------------------------------------------
extern "C" void kernel_launch(void* const* d_in, const int* in_sizes, int n_in,
                              void* d_out, int out_size) {
    const float* x      = (const float*)d_in[0];
    const int*   ei     = (const int*)  d_in[1];
    const int*   batch  = (const int*)  d_in[2];
    const float* lin1_W = (const float*)d_in[3];
    const float* lin1_b = (const float*)d_in[4];
    const float* Wna    = (const float*)d_in[5];
    const float* lna    = (const float*)d_in[6];
    const float* lro    = (const float*)d_in[7];
    const float* lout_W = (const float*)d_in[8];
    const float* lout_b = (const float*)d_in[9];
    const float* cls_W  = (const float*)d_in[10];
    const float* cls_b  = (const float*)d_in[11];
    const int* srcp = ei;
    const int* dstp = ei + NE;

    __half *x16, *h16A, *h16B, *s16, *m16, *g16, *pWh;
    int *pdeg, *prowptr, *pbhist, *pgstart;
    cudaGetSymbolAddress((void**)&x16,     d_x16);
    cudaGetSymbolAddress((void**)&h16A,    d_h16A);
    cudaGetSymbolAddress((void**)&h16B,    d_h16B);
    cudaGetSymbolAddress((void**)&s16,     d_s16);
    cudaGetSymbolAddress((void**)&m16,     d_m16);
    cudaGetSymbolAddress((void**)&g16,     d_g16);
    cudaGetSymbolAddress((void**)&pWh,     d_Wh);
    cudaGetSymbolAddress((void**)&pdeg,    d_deg);
    cudaGetSymbolAddress((void**)&prowptr, d_rowptr);
    cudaGetSymbolAddress((void**)&pbhist,  d_bhist);
    cudaGetSymbolAddress((void**)&pgstart, d_gstart);

    cudaFuncSetAttribute(k_gemm_f16,
                         cudaFuncAttributeMaxDynamicSharedMemorySize, GEMM_SMEM);

    int gblocks = (NN + 127) / 128;

    k_init<<<(NN+255)/256, 256>>>(lna, lro);
    k_tohalf<<<(NN*H/2+255)/256, 256>>>(x);
    k_wcomb<<<(NWMAT*HH+255)/256, 256>>>(Wna, lin1_W);
    // launch index 3 -> ncu capture lands here: lin1 GEMM
    k_gemm_f16<<<gblocks, 256, GEMM_SMEM>>>(x16, x16, x16, x16,
                                            pWh + (LAY*4)*HH, lin1_b,
                                            h16A, NN, 1, 0);
    k_hist<<<512, 256>>>(dstp, batch);
    k_scan1<<<NB_SCAN, 1024>>>(pdeg, prowptr, NN);
    k_scan2<<<1, 32>>>(prowptr, NN, NB_SCAN);
    k_scan3c<<<NB_SCAN, 1024>>>(prowptr, NN);
    k_scan_small<<<1, 1024>>>(pbhist, pgstart, NG);
    k_scatter<<<512, 256>>>(srcp, dstp);
    k_readout<<<NG, H>>>(h16A, 0);

    __half* cur16 = h16A;
    __half* nxt16 = h16B;
    for (int l = 0; l < LAY; l++) {
        k_aggregate<<<(NN*32+255)/256, 256>>>(cur16);
        k_gemm_f16<<<gblocks, 256, GEMM_SMEM>>>(cur16, m16, s16, g16,
                                                pWh + l*4*HH, nullptr,
                                                nxt16, NN, 4, 1);
        k_readout<<<NG, H>>>(nxt16, l+1);
        __half* t16 = cur16; cur16 = nxt16; nxt16 = t16;
    }
    k_head<<<NG, H>>>(lout_W, lout_b, cls_W, cls_b, (float*)d_out);
}

// round 9
// speedup vs baseline: 4.6977x; 1.0166x over previous
#include <cuda_runtime.h>
#include <cuda_fp16.h>
#include <math.h>
#include <stdint.h>

#define NN 50000
#define NE 800000
#define H 128
#define LAY 3
#define NG 512
#define NOUT 10
#define HH (H*H)
#define NB_SCAN ((NN + 1023) / 1024)
#define NWMAT (LAY*4 + 1)
#define STRIDE_H 40                // halves; 80B rows -> LDSM conflict-free
#define STAGE_H (128*STRIDE_H)
#define NSTAGE 3
#define GEMM_SMEM (2*NSTAGE*STAGE_H*2)   // 61440 B

// ---------------- scratch (static device globals) ---------------------------
__device__ __half   d_x16[NN*H];
__device__ __half   d_h16A[NN*H];
__device__ __half   d_h16B[NN*H];
__device__ __half   d_s16[NN*H];     // sum
__device__ __half   d_m16[NN*H];     // mean
__device__ __half   d_g16[NN*H];     // gcn
__device__ __half   d_Wh[NWMAT*HH];  // fp16 weights, [mat][n][k]
__device__ int      d_deg[NN];
__device__ int      d_rowptr[NN+1];
__device__ int      d_cursor[NN];
__device__ int      d_csr[NE];
__device__ float    d_invdeg[NN];
__device__ float    d_invsqrt[NN];
__device__ int      d_bhist[NG];
__device__ int      d_gstart[NG+1];
__device__ float    d_gfeat[NG*(LAY+1)*H];
__device__ int      d_btot[NB_SCAN];
__device__ int      d_boff[NB_SCAN];

// ---------------- helpers ----------------------------------------------------
__device__ __forceinline__ void cp16(uint32_t dst, const void* src, int sz) {
    asm volatile("cp.async.ca.shared.global [%0], [%1], 16, %2;"
                 :: "r"(dst), "l"(src), "r"(sz));
}
__device__ __forceinline__ void cp_commit() {
    asm volatile("cp.async.commit_group;");
}
template<int N>
__device__ __forceinline__ void cp_wait() {
    asm volatile("cp.async.wait_group %0;" :: "n"(N));
}

__device__ __forceinline__ void ldsm4(uint32_t& r0, uint32_t& r1, uint32_t& r2, uint32_t& r3,
                                      uint32_t addr) {
    asm volatile("ldmatrix.sync.aligned.m8n8.x4.shared.b16 {%0,%1,%2,%3}, [%4];"
                 : "=r"(r0), "=r"(r1), "=r"(r2), "=r"(r3) : "r"(addr));
}

__device__ __forceinline__ void mma_f16(float* acc,
                                        uint32_t a0, uint32_t a1, uint32_t a2, uint32_t a3,
                                        uint32_t b0, uint32_t b1) {
    asm volatile(
        "mma.sync.aligned.m16n8k16.row.col.f32.f16.f16.f32 "
        "{%0,%1,%2,%3}, {%4,%5,%6,%7}, {%8,%9}, {%0,%1,%2,%3};"
        : "+f"(acc[0]), "+f"(acc[1]), "+f"(acc[2]), "+f"(acc[3])
        : "r"(a0), "r"(a1), "r"(a2), "r"(a3), "r"(b0), "r"(b1));
}

// ---------------- x -> fp16, plus counter zeroing ----------------------------
__global__ void k_tohalf(const float* __restrict__ x) {
    int i = blockIdx.x*blockDim.x + threadIdx.x;
    if (i < NN*H/2) {
        float2 v = reinterpret_cast<const float2*>(x)[i];
        reinterpret_cast<__half2*>(d_x16)[i] = __floats2half2_rn(v.x, v.y);
    }
    if (i < NN) d_deg[i] = 0;
    if (i < NG) d_bhist[i] = 0;
}

// Combined per-layer weights, fp16, [mat][n][k]; softmax computed inline
__global__ void k_wcomb(const float* __restrict__ Wna, const float* __restrict__ lin1_W,
                        const float* __restrict__ lna) {
    int i = blockIdx.x*blockDim.x + threadIdx.x;
    if (i >= NWMAT*HH) return;
    int mat = i/HH; int e = i%HH;
    int k = e >> 7, n = e & 127;
    float v;
    if (mat < LAY*4) {
        int l = mat >> 2, s = mat & 3;
        float m = -1e30f;
        #pragma unroll
        for (int j = 0; j < 4; j++) m = fmaxf(m, lna[l*4+j]);
        float ex[4]; float sum = 0.f;
        #pragma unroll
        for (int j = 0; j < 4; j++) { ex[j] = expf(lna[l*4+j]-m); sum += ex[j]; }
        float na0 = ex[0]/sum, na1 = ex[1]/sum, na2 = ex[2]/sum, na3 = ex[3]/sum;
        const float* W = Wna + l*5*HH;
        int idx = k*H + n;
        if (s == 0)      v = na1*W[1*HH+idx] + na2*W[3*HH+idx] + na3*W[4*HH+idx];
        else if (s == 1) v = na1*W[2*HH+idx];
        else if (s == 2) v = na2*W[3*HH+idx];
        else             v = na0*W[0*HH+idx];
    } else {
        v = lin1_W[k*H + n];
    }
    d_Wh[mat*HH + n*H + k] = __float2half(v);
}

// vectorized histograms
__global__ void k_hist(const int* __restrict__ dst, const int* __restrict__ batch) {
    int i = blockIdx.x*blockDim.x + threadIdx.x;
    int stride = gridDim.x*blockDim.x;
    const int4* d4 = reinterpret_cast<const int4*>(dst);
    for (int e = i; e < NE/4; e += stride) {
        int4 v = d4[e];
        atomicAdd(&d_deg[v.x], 1);
        atomicAdd(&d_deg[v.y], 1);
        atomicAdd(&d_deg[v.z], 1);
        atomicAdd(&d_deg[v.w], 1);
    }
    const int2* b2 = reinterpret_cast<const int2*>(batch);
    for (int n = i; n < NN/2; n += stride) {
        int2 v = b2[n];
        atomicAdd(&d_bhist[v.x], 1);
        atomicAdd(&d_bhist[v.y], 1);
    }
}

// ---- hierarchical scan for NN ----
__global__ void k_scan1(const int* __restrict__ in, int* __restrict__ out, int n) {
    __shared__ int wsum[32];
    int i = blockIdx.x*1024 + threadIdx.x;
    int lane = threadIdx.x & 31, warp = threadIdx.x >> 5;
    int v = (i < n) ? in[i] : 0;
    int x = v;
    #pragma unroll
    for (int o = 1; o < 32; o <<= 1) {
        int y = __shfl_up_sync(0xffffffffu, x, o);
        if (lane >= o) x += y;
    }
    if (lane == 31) wsum[warp] = x;
    __syncthreads();
    if (warp == 0) {
        int s = wsum[lane];
        #pragma unroll
        for (int o = 1; o < 32; o <<= 1) {
            int y = __shfl_up_sync(0xffffffffu, s, o);
            if (lane >= o) s += y;
        }
        wsum[lane] = s;
    }
    __syncthreads();
    int incl = x + (warp ? wsum[warp-1] : 0);
    if (i < n) out[i] = incl - v;
    if (threadIdx.x == 1023) d_btot[blockIdx.x] = incl;
}

__global__ void k_scan2(int* __restrict__ out, int n, int nb) {
    if (threadIdx.x == 0) {
        int acc = 0;
        for (int b = 0; b < nb; b++) { d_boff[b] = acc; acc += d_btot[b]; }
        out[n] = acc;
    }
}

__global__ void k_scan3c(int* __restrict__ out, int n) {
    int i = blockIdx.x*blockDim.x + threadIdx.x;
    if (i >= n) return;
    int v = out[i] + d_boff[i >> 10];
    out[i] = v;
    d_cursor[i] = v;
    int c = d_deg[i];
    float m = (float)(c > 1 ? c : 1);
    d_invdeg[i]  = 1.0f/m;
    d_invsqrt[i] = rsqrtf(m);
}

__global__ void k_scan_small(const int* __restrict__ in, int* __restrict__ out, int n) {
    __shared__ int wsum[32];
    int lane = threadIdx.x & 31, warp = threadIdx.x >> 5;
    int i = threadIdx.x;
    int v = (i < n) ? in[i] : 0;
    int x = v;
    #pragma unroll
    for (int o = 1; o < 32; o <<= 1) {
        int y = __shfl_up_sync(0xffffffffu, x, o);
        if (lane >= o) x += y;
    }
    if (lane == 31) wsum[warp] = x;
    __syncthreads();
    if (warp == 0) {
        int s = wsum[lane];
        #pragma unroll
        for (int o = 1; o < 32; o <<= 1) {
            int y = __shfl_up_sync(0xffffffffu, s, o);
            if (lane >= o) s += y;
        }
        wsum[lane] = s;
    }
    __syncthreads();
    int incl = x + (warp ? wsum[warp-1] : 0);
    if (i < n) out[i] = incl - v;
    if (i == n-1) out[n] = incl;
}

__global__ void k_scatter(const int* __restrict__ src, const int* __restrict__ dst) {
    int i = blockIdx.x*blockDim.x + threadIdx.x;
    int stride = gridDim.x*blockDim.x;
    const int4* s4 = reinterpret_cast<const int4*>(src);
    const int4* d4 = reinterpret_cast<const int4*>(dst);
    for (int e = i; e < NE/4; e += stride) {
        int4 sv = s4[e];
        int4 dv = d4[e];
        d_csr[atomicAdd(&d_cursor[dv.x], 1)] = sv.x;
        d_csr[atomicAdd(&d_cursor[dv.y], 1)] = sv.y;
        d_csr[atomicAdd(&d_cursor[dv.z], 1)] = sv.z;
        d_csr[atomicAdd(&d_cursor[dv.w], 1)] = sv.w;
    }
}

// ---------------- aggregation: one warp per dst node; all fp16 --------------
__global__ void k_aggregate(const __half* __restrict__ h16) {
    int gw   = (blockIdx.x*blockDim.x + threadIdx.x) >> 5;
    int lane = threadIdx.x & 31;
    if (gw >= NN) return;
    int beg = d_rowptr[gw], end = d_rowptr[gw+1];
    const uint2* h2 = reinterpret_cast<const uint2*>(h16);
    float4 s = {0.f,0.f,0.f,0.f};
    float4 g = {0.f,0.f,0.f,0.f};
    for (int e = beg; e < end; e++) {
        int src  = d_csr[e];
        float is = d_invsqrt[src];
        uint2 raw = h2[src*32 + lane];
        float2 lo = __half22float2(*reinterpret_cast<const __half2*>(&raw.x));
        float2 hi = __half22float2(*reinterpret_cast<const __half2*>(&raw.y));
        s.x += lo.x;    s.y += lo.y;    s.z += hi.x;    s.w += hi.y;
        g.x += lo.x*is; g.y += lo.y*is; g.z += hi.x*is; g.w += hi.y*is;
    }
    float id  = d_invdeg[gw];
    float isd = d_invsqrt[gw];
    int o = gw*32 + lane;
    uint2 su, mu, gu;
    *reinterpret_cast<__half2*>(&su.x) = __floats2half2_rn(s.x, s.y);
    *reinterpret_cast<__half2*>(&su.y) = __floats2half2_rn(s.z, s.w);
    *reinterpret_cast<__half2*>(&mu.x) = __floats2half2_rn(s.x*id, s.y*id);
    *reinterpret_cast<__half2*>(&mu.y) = __floats2half2_rn(s.z*id, s.w*id);
    *reinterpret_cast<__half2*>(&gu.x) = __floats2half2_rn(g.x*isd, g.y*isd);
    *reinterpret_cast<__half2*>(&gu.y) = __floats2half2_rn(g.z*isd, g.w*isd);
    reinterpret_cast<uint2*>(d_s16)[o] = su;
    reinterpret_cast<uint2*>(d_m16)[o] = mu;
    reinterpret_cast<uint2*>(d_g16)[o] = gu;
}

// ---------------- FP16 GEMM: 3-stage cp.async, 1 barrier/chunk ---------------
// out16[M,128] = sum_s A_s @ W_s  (+bias) (relu)
__global__ void __launch_bounds__(256)
k_gemm_f16(const __half* __restrict__ A0, const __half* __restrict__ A1,
           const __half* __restrict__ A2, const __half* __restrict__ A3,
           const __half* __restrict__ Wh,     // [nsrc][128][128] fp16 n-major
           const float* __restrict__ bias,
           __half* __restrict__ out16, int M, int nsrc, int relu)
{
    extern __shared__ char smem[];
    __half* AsH = (__half*)smem;                      // [NSTAGE][STAGE_H]
    __half* BsH = (__half*)smem + NSTAGE*STAGE_H;     // [NSTAGE][STAGE_H]
    uint32_t asAddr = (uint32_t)__cvta_generic_to_shared(AsH);
    uint32_t bsAddr = (uint32_t)__cvta_generic_to_shared(BsH);

    const __half* srcs[4] = {A0, A1, A2, A3};
    int tid  = threadIdx.x;
    int lane = tid & 31;
    int wid  = tid >> 5;
    int wm = (wid & 3) * 32;
    int wn = (wid >> 2) * 64;
    int lr = lane >> 2, lc = lane & 3;
    int row0 = blockIdx.x * 128;

    uint32_t aoff = ((wm + (lane & 15)) * STRIDE_H + ((lane >> 4) << 3)) * 2;
    uint32_t boff = ((wn + (lane & 7) + ((lane & 16) >> 1)) * STRIDE_H + (lane & 8)) * 2;

    float acc[2][8][4];
    #pragma unroll
    for (int mt = 0; mt < 2; mt++)
        #pragma unroll
        for (int nt = 0; nt < 8; nt++)
            #pragma unroll
            for (int c = 0; c < 4; c++) acc[mt][nt][c] = 0.f;

    const int C = nsrc * 4;

    auto issue = [&](int c) {
        int st = c % NSTAGE;
        int s  = c >> 2;
        int k0 = (c & 3) * 32;
        const __half* A  = srcs[s];
        const __half* Wb = Wh + s*HH;
        #pragma unroll
        for (int i = 0; i < 2; i++) {
            int idx = tid + i*256;
            int m = idx >> 2, kg = (idx & 3) * 8;
            int r = row0 + m;
            const __half* src = A + (size_t)(r < M ? r : 0)*H + k0 + kg;
            cp16(asAddr + (st*STAGE_H + m*STRIDE_H + kg)*2, src, (r < M) ? 16 : 0);
        }
        #pragma unroll
        for (int i = 0; i < 2; i++) {
            int idx = tid + i*256;
            int n = idx >> 2, kg = (idx & 3) * 8;
            cp16(bsAddr + (st*STAGE_H + n*STRIDE_H + kg)*2, Wb + n*H + k0 + kg, 16);
        }
        cp_commit();
    };

    issue(0);
    if (C > 1) issue(1);
    for (int c = 0; c < C; c++) {
        if (c < C-1) cp_wait<1>(); else cp_wait<0>();
        __syncthreads();
        if (c + 2 < C) issue(c + 2);

        int st = c % NSTAGE;
        uint32_t aBase = asAddr + st*STAGE_H*2 + aoff;
        uint32_t bBase = bsAddr + st*STAGE_H*2 + boff;

        #pragma unroll
        for (int kb = 0; kb < 32; kb += 16) {
            uint32_t a[2][4];
            #pragma unroll
            for (int mt = 0; mt < 2; mt++)
                ldsm4(a[mt][0], a[mt][1], a[mt][2], a[mt][3],
                      aBase + (mt*16*STRIDE_H + kb)*2);
            uint32_t b[4][4];
            #pragma unroll
            for (int j = 0; j < 4; j++)
                ldsm4(b[j][0], b[j][1], b[j][2], b[j][3],
                      bBase + (j*16*STRIDE_H + kb)*2);
            #pragma unroll
            for (int mt = 0; mt < 2; mt++)
                #pragma unroll
                for (int j = 0; j < 4; j++) {
                    mma_f16(acc[mt][2*j],   a[mt][0], a[mt][1], a[mt][2], a[mt][3],
                            b[j][0], b[j][1]);
                    mma_f16(acc[mt][2*j+1], a[mt][0], a[mt][1], a[mt][2], a[mt][3],
                            b[j][2], b[j][3]);
                }
        }
    }

    // epilogue: fp16 out
    #pragma unroll
    for (int mt = 0; mt < 2; mt++) {
        int r0 = row0 + wm + mt*16 + lr;
        int r1 = r0 + 8;
        #pragma unroll
        for (int nt = 0; nt < 8; nt++) {
            int c = wn + nt*8 + 2*lc;
            float b0 = bias ? bias[c]   : 0.f;
            float b1 = bias ? bias[c+1] : 0.f;
            float v0 = acc[mt][nt][0] + b0;
            float v1 = acc[mt][nt][1] + b1;
            float v2 = acc[mt][nt][2] + b0;
            float v3 = acc[mt][nt][3] + b1;
            if (relu) {
                v0 = fmaxf(v0, 0.f); v1 = fmaxf(v1, 0.f);
                v2 = fmaxf(v2, 0.f); v3 = fmaxf(v3, 0.f);
            }
            if (r0 < M)
                *reinterpret_cast<__half2*>(out16 + r0*H + c) = __floats2half2_rn(v0, v1);
            if (r1 < M)
                *reinterpret_cast<__half2*>(out16 + r1*H + c) = __floats2half2_rn(v2, v3);
        }
    }
}

// ---------------- readout: softmax inline -----------------------------------
__global__ void k_readout(const __half* __restrict__ h16, const float* __restrict__ lro,
                          int layer) {
    int gr = blockIdx.x;
    int c  = threadIdx.x;
    int beg = d_gstart[gr], end = d_gstart[gr+1];
    float s = 0.f, mx = -3.4e38f;
    for (int n = beg; n < end; n++) {
        float v = __half2float(h16[n*H + c]);
        s += v;
        mx = fmaxf(mx, v);
    }
    int cnt = end - beg;
    float mean = s / (float)(cnt > 1 ? cnt : 1);
    if (cnt == 0) mx = 0.f;
    float m = fmaxf(lro[layer*3], fmaxf(lro[layer*3+1], lro[layer*3+2]));
    float e0 = expf(lro[layer*3]-m), e1 = expf(lro[layer*3+1]-m), e2 = expf(lro[layer*3+2]-m);
    float inv = 1.f/(e0+e1+e2);
    d_gfeat[gr*((LAY+1)*H) + layer*H + c] = (e0*mean + e1*mx + e2*s)*inv;
}

// ---------------- head ------------------------------------------------------
__global__ void k_head(const float* __restrict__ Wl, const float* __restrict__ bl,
                       const float* __restrict__ Wc, const float* __restrict__ bc,
                       float* __restrict__ out) {
    __shared__ float sg[(LAY+1)*H];
    __shared__ float mid[H];
    int gr = blockIdx.x;
    int t  = threadIdx.x;
    for (int i = t; i < (LAY+1)*H; i += H) sg[i] = d_gfeat[gr*((LAY+1)*H) + i];
    __syncthreads();
    float acc = bl[t];
    for (int k = 0; k < (LAY+1)*H; k++) acc += sg[k]*Wl[k*H + t];
    mid[t] = fmaxf(acc, 0.f);
    __syncthreads();
    if (t < NOUT) {
        float a = bc[t];
        for (int k = 0; k < H; k++) a += mid[k]*Wc[k*NOUT + t];
        out[gr*NOUT + t] = a;
    }
}

// ---------------- launch ----------------------------------------------------
extern "C" void kernel_launch(void* const* d_in, const int* in_sizes, int n_in,
                              void* d_out, int out_size) {
    const float* x      = (const float*)d_in[0];
    const int*   ei     = (const int*)  d_in[1];
    const int*   batch  = (const int*)  d_in[2];
    const float* lin1_W = (const float*)d_in[3];
    const float* lin1_b = (const float*)d_in[4];
    const float* Wna    = (const float*)d_in[5];
    const float* lna    = (const float*)d_in[6];
    const float* lro    = (const float*)d_in[7];
    const float* lout_W = (const float*)d_in[8];
    const float* lout_b = (const float*)d_in[9];
    const float* cls_W  = (const float*)d_in[10];
    const float* cls_b  = (const float*)d_in[11];
    const int* srcp = ei;
    const int* dstp = ei + NE;

    __half *x16, *h16A, *h16B, *s16, *m16, *g16, *pWh;
    int *pdeg, *prowptr, *pbhist, *pgstart;
    cudaGetSymbolAddress((void**)&x16,     d_x16);
    cudaGetSymbolAddress((void**)&h16A,    d_h16A);
    cudaGetSymbolAddress((void**)&h16B,    d_h16B);
    cudaGetSymbolAddress((void**)&s16,     d_s16);
    cudaGetSymbolAddress((void**)&m16,     d_m16);
    cudaGetSymbolAddress((void**)&g16,     d_g16);
    cudaGetSymbolAddress((void**)&pWh,     d_Wh);
    cudaGetSymbolAddress((void**)&pdeg,    d_deg);
    cudaGetSymbolAddress((void**)&prowptr, d_rowptr);
    cudaGetSymbolAddress((void**)&pbhist,  d_bhist);
    cudaGetSymbolAddress((void**)&pgstart, d_gstart);

    cudaFuncSetAttribute(k_gemm_f16,
                         cudaFuncAttributeMaxDynamicSharedMemorySize, GEMM_SMEM);

    int gblocks = (NN + 127) / 128;

    k_tohalf<<<(NN*H/2+255)/256, 256>>>(x);
    k_wcomb<<<(NWMAT*HH+255)/256, 256>>>(Wna, lin1_W, lna);
    k_gemm_f16<<<gblocks, 256, GEMM_SMEM>>>(x16, x16, x16, x16,
                                            pWh + (LAY*4)*HH, lin1_b,
                                            h16A, NN, 1, 0);
    k_hist<<<512, 256>>>(dstp, batch);
    k_scan1<<<NB_SCAN, 1024>>>(pdeg, prowptr, NN);
    k_scan2<<<1, 32>>>(prowptr, NN, NB_SCAN);
    k_scan3c<<<NB_SCAN, 1024>>>(prowptr, NN);
    k_scan_small<<<1, 1024>>>(pbhist, pgstart, NG);
    k_scatter<<<512, 256>>>(srcp, dstp);
    k_readout<<<NG, H>>>(h16A, lro, 0);

    __half* cur16 = h16A;
    __half* nxt16 = h16B;
    for (int l = 0; l < LAY; l++) {
        k_aggregate<<<(NN*32+255)/256, 256>>>(cur16);
        k_gemm_f16<<<gblocks, 256, GEMM_SMEM>>>(cur16, m16, s16, g16,
                                                pWh + l*4*HH, nullptr,
                                                nxt16, NN, 4, 1);
        k_readout<<<NG, H>>>(nxt16, lro, l+1);
        __half* t16 = cur16; cur16 = nxt16; nxt16 = t16;
    }
    k_head<<<NG, H>>>(lout_W, lout_b, cls_W, cls_b, (float*)d_out);
}